// round 4
// baseline (speedup 1.0000x reference)
#include <cuda_runtime.h>
#include <math.h>
#include <stdint.h>

#define BB     2048
#define TT     256
#define EMB    128
#define NH     256
#define NCLASS 32000
#define KB     32

// -------- persistent scratch (static device globals; no allocation) --------
__device__ float g_xU0[(size_t)128 * BB * 1024];
__device__ float g_xU1[(size_t)128 * BB * 1024];
__device__ float g_W1p[256 * 1024];   // packed V*1  [k][4n+g], tf32-rounded
__device__ float g_W2p[512 * 1024];   // packed [U*2 ; V*2]
__device__ float g_U1p[128 * 1024];   // packed U*1 for xU gemm
__device__ float g_bp[1024];          // packed biases (fp32)
__device__ float g_h1[2][BB * NH];
__device__ float g_h2[2][BB * NH];
__device__ float g_c1[BB * NH];
__device__ float g_c2[BB * NH];

// -------- helpers --------
__device__ __forceinline__ uint32_t f2tf(float x) {
    uint32_t r; asm("cvt.rna.tf32.f32 %0, %1;" : "=r"(r) : "f"(x)); return r;
}
__device__ __forceinline__ float sigf(float x) { return 1.f / (1.f + __expf(-x)); }
__device__ __forceinline__ float tanhfa(float x) { return 2.f / (1.f + __expf(-2.f * x)) - 1.f; }

__device__ __forceinline__ void mma_tf32(float c[4], const uint32_t a[4], const uint32_t b[2]) {
    asm volatile(
        "mma.sync.aligned.m16n8k8.row.col.f32.tf32.tf32.f32 "
        "{%0,%1,%2,%3}, {%4,%5,%6,%7}, {%8,%9}, {%0,%1,%2,%3};\n"
        : "+f"(c[0]), "+f"(c[1]), "+f"(c[2]), "+f"(c[3])
        : "r"(a[0]), "r"(a[1]), "r"(a[2]), "r"(a[3]), "r"(b[0]), "r"(b[1]));
}

// -------- weight packing: dst[k][4n+g] = tf32(src_g[k][n]) --------
__global__ void pack4(float* dst, const float* s0, const float* s1,
                      const float* s2, const float* s3, int K) {
    int i = blockIdx.x * blockDim.x + threadIdx.x;
    if (i < K * 256) {
        int base = (i >> 8) * 1024 + ((i & 255) << 2);
        dst[base + 0] = __uint_as_float(f2tf(s0[i]));
        dst[base + 1] = __uint_as_float(f2tf(s1[i]));
        dst[base + 2] = __uint_as_float(f2tf(s2[i]));
        dst[base + 3] = __uint_as_float(f2tf(s3[i]));
    }
}

__global__ void pack_b(const float* b0, const float* b1, const float* b2, const float* b3) {
    int n = threadIdx.x;
    g_bp[4 * n + 0] = b0[n];
    g_bp[4 * n + 1] = b1[n];
    g_bp[4 * n + 2] = b2[n];
    g_bp[4 * n + 3] = b3[n];
}

__global__ void zero_states() {
    const int n = BB * NH;
    for (int i = blockIdx.x * blockDim.x + threadIdx.x; i < n; i += gridDim.x * blockDim.x) {
        g_h1[0][i] = 0.f; g_h2[0][i] = 0.f; g_c1[i] = 0.f; g_c2[i] = 0.f;
    }
}

// ==========================================================================
// xU precompute: xU[t*2048+b][c] = sum_k tf32(C[X[b][t]][k]) * U1p[k][c] + bp[c]
// M = 524288, N = 1024, K = 128.  Tile 128x128, KB=32.
// ==========================================================================
__global__ __launch_bounds__(256) void xu_gemm(const int* __restrict__ X,
                                               const float* __restrict__ C) {
    __shared__ float sA[KB][136];
    __shared__ float sB[KB][136];
    const int tid = threadIdx.x;
    const int warp = tid >> 5, lane = tid & 31;
    const int gid = lane >> 2, tig = lane & 3;
    const int wR = warp >> 2, wC = warp & 3;
    const int mBase = blockIdx.y * 128;
    const int nBase = blockIdx.x * 128;

    const int arow = tid >> 1;
    const int r_glob = mBase + arow;
    const int t_idx = r_glob >> 11, b_idx = r_glob & 2047;
    const int tok = X[b_idx * TT + t_idx];
    const float* Arow = C + (size_t)tok * EMB;
    const int kq0 = (tid & 1) * 4;

    float acc[4][4][4];
#pragma unroll
    for (int mt = 0; mt < 4; ++mt)
#pragma unroll
        for (int nt = 0; nt < 4; ++nt)
#pragma unroll
            for (int q = 0; q < 4; ++q) acc[mt][nt][q] = 0.f;

    float4 pa[4], pb[4];
#pragma unroll
    for (int i = 0; i < 4; ++i)
        pa[i] = *(const float4*)&Arow[(kq0 + i) * 4];
#pragma unroll
    for (int i = 0; i < 4; ++i) {
        int id = tid * 4 + i; int k = id >> 5, n4 = (id & 31) * 4;
        pb[i] = *(const float4*)&g_U1p[(size_t)k * 1024 + nBase + n4];
    }

#pragma unroll 1
    for (int kb = 0; kb < EMB; kb += KB) {
#pragma unroll
        for (int i = 0; i < 4; ++i) {
            int kk = (kq0 + i) * 4;
            sA[kk + 0][arow] = __uint_as_float(f2tf(pa[i].x));
            sA[kk + 1][arow] = __uint_as_float(f2tf(pa[i].y));
            sA[kk + 2][arow] = __uint_as_float(f2tf(pa[i].z));
            sA[kk + 3][arow] = __uint_as_float(f2tf(pa[i].w));
        }
#pragma unroll
        for (int i = 0; i < 4; ++i) {
            int id = tid * 4 + i; int k = id >> 5, n4 = (id & 31) * 4;
            *(float4*)&sB[k][n4] = pb[i];
        }
        __syncthreads();
        if (kb + KB < EMB) {
#pragma unroll
            for (int i = 0; i < 4; ++i)
                pa[i] = *(const float4*)&Arow[kb + KB + (kq0 + i) * 4];
#pragma unroll
            for (int i = 0; i < 4; ++i) {
                int id = tid * 4 + i; int k = id >> 5, n4 = (id & 31) * 4;
                pb[i] = *(const float4*)&g_U1p[(size_t)(kb + KB + k) * 1024 + nBase + n4];
            }
        }
#pragma unroll
        for (int k8 = 0; k8 < KB; k8 += 8) {
            uint32_t af[4][4], bf_[4][2];
#pragma unroll
            for (int mt = 0; mt < 4; ++mt) {
                int r = wR * 64 + mt * 16 + gid;
                af[mt][0] = __float_as_uint(sA[k8 + tig][r]);
                af[mt][1] = __float_as_uint(sA[k8 + tig][r + 8]);
                af[mt][2] = __float_as_uint(sA[k8 + tig + 4][r]);
                af[mt][3] = __float_as_uint(sA[k8 + tig + 4][r + 8]);
            }
#pragma unroll
            for (int nt = 0; nt < 4; ++nt) {
                int c = wC * 32 + nt * 8 + gid;
                bf_[nt][0] = __float_as_uint(sB[k8 + tig][c]);
                bf_[nt][1] = __float_as_uint(sB[k8 + tig + 4][c]);
            }
#pragma unroll
            for (int mt = 0; mt < 4; ++mt)
#pragma unroll
                for (int nt = 0; nt < 4; ++nt)
                    mma_tf32(acc[mt][nt], af[mt], bf_[nt]);
        }
        __syncthreads();
    }

    const int t_tile = mBase >> 11;
    float* xu = (t_tile < 128) ? g_xU0 : g_xU1;
    const size_t rowoff = (size_t)(mBase & ((128 << 11) - 1));
#pragma unroll
    for (int nt = 0; nt < 4; ++nt) {
        int c0 = nBase + wC * 32 + nt * 8 + 2 * tig;
        float2 bb = *(const float2*)&g_bp[c0];
#pragma unroll
        for (int mt = 0; mt < 4; ++mt) {
            int r0 = wR * 64 + mt * 16 + gid;
            float2 v0 = make_float2(acc[mt][nt][0] + bb.x, acc[mt][nt][1] + bb.y);
            float2 v1 = make_float2(acc[mt][nt][2] + bb.x, acc[mt][nt][3] + bb.y);
            *(float2*)&xu[(rowoff + r0) * 1024 + c0] = v0;
            *(float2*)&xu[(rowoff + r0 + 8) * 1024 + c0] = v1;
        }
    }
}

// ==========================================================================
// Paired LSTM step: one launch computes L1(t) [CTAs 0..127] and L0(t+1)
// [CTAs 128..255] concurrently. They are independent:
//   L1(t):  gates = h1[(t+1)&1] @ U*2 + h2[t&1] @ V*2 + b  -> h2[(t+1)&1], c2
//   L0(t+1): gates = xU[t+1] + h1[(t+1)&1] @ V*1           -> h1[t&1],    c1
// t = -1 runs only L0(0).  Tile 128x128(packed), 256 threads.
// ==========================================================================
__global__ __launch_bounds__(256) void step_pair(int t) {
    const int part = blockIdx.x >> 7;        // 0 = L1(t), 1 = L0(t+1)
    if (part == 0 && t < 0) return;
    if (part == 1 && t + 1 >= TT) return;

    __shared__ float sA[KB][136];
    __shared__ float sB[KB][136];
    const int tid = threadIdx.x;
    const int warp = tid >> 5, lane = tid & 31;
    const int gid = lane >> 2, tig = lane & 3;
    const int wR = warp >> 2, wC = warp & 3;
    const int bid = blockIdx.x & 127;
    const int mBase = (bid >> 3) * 128;
    const int nBase = (bid & 7) * 128;

    const int layer = (part == 0) ? 1 : 0;
    const int ts = (part == 0) ? t : t + 1;

    const float* A0; const float* A1; const float* Wp; int K;
    float* cst; float* hout;
    if (layer == 0) {
        A0 = g_h1[ts & 1]; A1 = A0; Wp = g_W1p; K = 256;
        cst = g_c1; hout = g_h1[(ts + 1) & 1];
    } else {
        A0 = g_h1[(ts + 1) & 1]; A1 = g_h2[ts & 1]; Wp = g_W2p; K = 512;
        cst = g_c2; hout = g_h2[(ts + 1) & 1];
    }

    float acc[4][4][4];
#pragma unroll
    for (int mt = 0; mt < 4; ++mt)
#pragma unroll
        for (int nt = 0; nt < 4; ++nt)
#pragma unroll
            for (int q = 0; q < 4; ++q) acc[mt][nt][q] = 0.f;

    const int arow = tid >> 1;
    const int kq0 = (tid & 1) * 4;

    float4 pa[4], pb[4];
#pragma unroll
    for (int i = 0; i < 4; ++i)
        pa[i] = *(const float4*)&A0[(size_t)(mBase + arow) * NH + (kq0 + i) * 4];
#pragma unroll
    for (int i = 0; i < 4; ++i) {
        int id = tid * 4 + i; int k = id >> 5, n4 = (id & 31) * 4;
        pb[i] = *(const float4*)&Wp[(size_t)k * 1024 + nBase + n4];
    }

#pragma unroll 1
    for (int kb = 0; kb < K; kb += KB) {
#pragma unroll
        for (int i = 0; i < 4; ++i) {
            int kk = (kq0 + i) * 4;
            sA[kk + 0][arow] = __uint_as_float(f2tf(pa[i].x));
            sA[kk + 1][arow] = __uint_as_float(f2tf(pa[i].y));
            sA[kk + 2][arow] = __uint_as_float(f2tf(pa[i].z));
            sA[kk + 3][arow] = __uint_as_float(f2tf(pa[i].w));
        }
#pragma unroll
        for (int i = 0; i < 4; ++i) {
            int id = tid * 4 + i; int k = id >> 5, n4 = (id & 31) * 4;
            *(float4*)&sB[k][n4] = pb[i];
        }
        __syncthreads();
        if (kb + KB < K) {
            int kn = kb + KB;
            const float* Asrc = (kn < 256) ? A0 : A1;
            int kk = kn & 255;
#pragma unroll
            for (int i = 0; i < 4; ++i)
                pa[i] = *(const float4*)&Asrc[(size_t)(mBase + arow) * NH + kk + (kq0 + i) * 4];
#pragma unroll
            for (int i = 0; i < 4; ++i) {
                int id = tid * 4 + i; int k = id >> 5, n4 = (id & 31) * 4;
                pb[i] = *(const float4*)&Wp[(size_t)(kn + k) * 1024 + nBase + n4];
            }
        }
#pragma unroll
        for (int k8 = 0; k8 < KB; k8 += 8) {
            uint32_t af[4][4], bf_[4][2];
#pragma unroll
            for (int mt = 0; mt < 4; ++mt) {
                int r = wR * 64 + mt * 16 + gid;
                af[mt][0] = __float_as_uint(sA[k8 + tig][r]);
                af[mt][1] = __float_as_uint(sA[k8 + tig][r + 8]);
                af[mt][2] = __float_as_uint(sA[k8 + tig + 4][r]);
                af[mt][3] = __float_as_uint(sA[k8 + tig + 4][r + 8]);
            }
#pragma unroll
            for (int nt = 0; nt < 4; ++nt) {
                int c = wC * 32 + nt * 8 + gid;
                bf_[nt][0] = __float_as_uint(sB[k8 + tig][c]);
                bf_[nt][1] = __float_as_uint(sB[k8 + tig + 4][c]);
            }
#pragma unroll
            for (int mt = 0; mt < 4; ++mt)
#pragma unroll
                for (int nt = 0; nt < 4; ++nt)
                    mma_tf32(acc[mt][nt], af[mt], bf_[nt]);
        }
        __syncthreads();
    }

    // ---- fused LSTM cell epilogue ----
    const float* xu = (ts < 128) ? g_xU0 : g_xU1;
    const size_t xu_t = (size_t)(ts & 127) * BB * 1024;
    const bool tlow = ((tig & 1) == 0);
#pragma unroll
    for (int nt = 0; nt < 4; ++nt) {
        int c0 = nBase + wC * 32 + nt * 8 + 2 * tig;
        int n = c0 >> 2;
#pragma unroll
        for (int mt = 0; mt < 4; ++mt) {
            float q0 = acc[mt][nt][0], q1 = acc[mt][nt][1];
            float q2 = acc[mt][nt][2], q3 = acc[mt][nt][3];
            float x0 = tlow ? q2 : q0;
            float x1 = tlow ? q3 : q1;
            float y0 = __shfl_xor_sync(0xffffffffu, x0, 1);
            float y1 = __shfl_xor_sync(0xffffffffu, x1, 1);
            float gI, gF, gG, gO;
            int row;
            if (tlow) { gI = q0; gF = q1; gG = y0; gO = y1; row = mBase + wR * 64 + mt * 16 + gid; }
            else      { gI = y0; gF = y1; gG = q2; gO = q3; row = mBase + wR * 64 + mt * 16 + gid + 8; }
            float a0, a1, a2, a3;
            if (layer == 0) {
                float4 x4 = *(const float4*)&xu[xu_t + (size_t)row * 1024 + (n << 2)];
                a0 = x4.x; a1 = x4.y; a2 = x4.z; a3 = x4.w;
            } else {
                float4 b4 = *(const float4*)&g_bp[n << 2];
                a0 = b4.x; a1 = b4.y; a2 = b4.z; a3 = b4.w;
            }
            float si = sigf(gI + a0);
            float sf = sigf(gF + a1);
            float sg = tanhfa(gG + a2);
            float so = sigf(gO + a3);
            size_t off = (size_t)row * NH + n;
            float cn = cst[off] * sf + si * sg;
            cst[off] = cn;
            hout[off] = so * tanhfa(cn);
        }
    }
}

// ==========================================================================
// Output GEMM: out = h2 @ W_out + b_out.  M=2048, N=32000, K=256.
// ==========================================================================
__global__ __launch_bounds__(256) void out_gemm_mma(const float* __restrict__ Wout,
                                                    const float* __restrict__ bout,
                                                    float* __restrict__ out) {
    __shared__ float sA[KB][136];
    __shared__ float sB[KB][136];
    const int tid = threadIdx.x;
    const int warp = tid >> 5, lane = tid & 31;
    const int gid = lane >> 2, tig = lane & 3;
    const int wR = warp >> 2, wC = warp & 3;
    const int mBase = blockIdx.y * 128;
    const int nBase = blockIdx.x * 128;
    const float* h2 = g_h2[0];

    float acc[4][4][4];
#pragma unroll
    for (int mt = 0; mt < 4; ++mt)
#pragma unroll
        for (int nt = 0; nt < 4; ++nt)
#pragma unroll
            for (int q = 0; q < 4; ++q) acc[mt][nt][q] = 0.f;

    const int arow = tid >> 1;
    const int kq0 = (tid & 1) * 4;

    float4 pa[4], pb[4];
#pragma unroll
    for (int i = 0; i < 4; ++i)
        pa[i] = *(const float4*)&h2[(size_t)(mBase + arow) * NH + (kq0 + i) * 4];
#pragma unroll
    for (int i = 0; i < 4; ++i) {
        int id = tid * 4 + i; int k = id >> 5, n4 = (id & 31) * 4;
        pb[i] = *(const float4*)&Wout[(size_t)k * NCLASS + nBase + n4];
    }

#pragma unroll 1
    for (int kb = 0; kb < NH; kb += KB) {
#pragma unroll
        for (int i = 0; i < 4; ++i) {
            int kk = (kq0 + i) * 4;
            sA[kk + 0][arow] = __uint_as_float(f2tf(pa[i].x));
            sA[kk + 1][arow] = __uint_as_float(f2tf(pa[i].y));
            sA[kk + 2][arow] = __uint_as_float(f2tf(pa[i].z));
            sA[kk + 3][arow] = __uint_as_float(f2tf(pa[i].w));
        }
#pragma unroll
        for (int i = 0; i < 4; ++i) {
            int id = tid * 4 + i; int k = id >> 5, n4 = (id & 31) * 4;
            float4 v = pb[i];
            v.x = __uint_as_float(f2tf(v.x)); v.y = __uint_as_float(f2tf(v.y));
            v.z = __uint_as_float(f2tf(v.z)); v.w = __uint_as_float(f2tf(v.w));
            *(float4*)&sB[k][n4] = v;
        }
        __syncthreads();
        if (kb + KB < NH) {
#pragma unroll
            for (int i = 0; i < 4; ++i)
                pa[i] = *(const float4*)&h2[(size_t)(mBase + arow) * NH + kb + KB + (kq0 + i) * 4];
#pragma unroll
            for (int i = 0; i < 4; ++i) {
                int id = tid * 4 + i; int k = id >> 5, n4 = (id & 31) * 4;
                pb[i] = *(const float4*)&Wout[(size_t)(kb + KB + k) * NCLASS + nBase + n4];
            }
        }
#pragma unroll
        for (int k8 = 0; k8 < KB; k8 += 8) {
            uint32_t af[4][4], bf_[4][2];
#pragma unroll
            for (int mt = 0; mt < 4; ++mt) {
                int r = wR * 64 + mt * 16 + gid;
                af[mt][0] = __float_as_uint(sA[k8 + tig][r]);
                af[mt][1] = __float_as_uint(sA[k8 + tig][r + 8]);
                af[mt][2] = __float_as_uint(sA[k8 + tig + 4][r]);
                af[mt][3] = __float_as_uint(sA[k8 + tig + 4][r + 8]);
            }
#pragma unroll
            for (int nt = 0; nt < 4; ++nt) {
                int c = wC * 32 + nt * 8 + gid;
                bf_[nt][0] = __float_as_uint(sB[k8 + tig][c]);
                bf_[nt][1] = __float_as_uint(sB[k8 + tig + 4][c]);
            }
#pragma unroll
            for (int mt = 0; mt < 4; ++mt)
#pragma unroll
                for (int nt = 0; nt < 4; ++nt)
                    mma_tf32(acc[mt][nt], af[mt], bf_[nt]);
        }
        __syncthreads();
    }

#pragma unroll
    for (int nt = 0; nt < 4; ++nt) {
        int c0 = nBase + wC * 32 + nt * 8 + 2 * tig;
        float2 bb = *(const float2*)&bout[c0];
#pragma unroll
        for (int mt = 0; mt < 4; ++mt) {
            int r0 = mBase + wR * 64 + mt * 16 + gid;
            float2 v0 = make_float2(acc[mt][nt][0] + bb.x, acc[mt][nt][1] + bb.y);
            float2 v1 = make_float2(acc[mt][nt][2] + bb.x, acc[mt][nt][3] + bb.y);
            *(float2*)&out[(size_t)r0 * NCLASS + c0] = v0;
            *(float2*)&out[(size_t)(r0 + 8) * NCLASS + c0] = v1;
        }
    }
}

// -------- launch --------
extern "C" void kernel_launch(void* const* d_in, const int* in_sizes, int n_in,
                              void* d_out, int out_size) {
    (void)in_sizes; (void)n_in; (void)out_size;
    const int*   X    = (const int*)d_in[0];
    const float* C    = (const float*)d_in[1];
    const float* Ui1  = (const float*)d_in[2];
    const float* Vi1  = (const float*)d_in[3];
    const float* Ui2  = (const float*)d_in[4];
    const float* Vi2  = (const float*)d_in[5];
    const float* bi   = (const float*)d_in[6];
    const float* Uf1  = (const float*)d_in[7];
    const float* Vf1  = (const float*)d_in[8];
    const float* Uf2  = (const float*)d_in[9];
    const float* Vf2  = (const float*)d_in[10];
    const float* bf   = (const float*)d_in[11];
    const float* Uc1  = (const float*)d_in[12];
    const float* Vc1  = (const float*)d_in[13];
    const float* Uc2  = (const float*)d_in[14];
    const float* Vc2  = (const float*)d_in[15];
    const float* bc   = (const float*)d_in[16];
    const float* Uo1  = (const float*)d_in[17];
    const float* Vo1  = (const float*)d_in[18];
    const float* Uo2  = (const float*)d_in[19];
    const float* Vo2  = (const float*)d_in[20];
    const float* bo   = (const float*)d_in[21];
    const float* Wout = (const float*)d_in[22];
    const float* bout = (const float*)d_in[23];
    float* out = (float*)d_out;

    float* W1p; cudaGetSymbolAddress((void**)&W1p, g_W1p);
    float* W2p; cudaGetSymbolAddress((void**)&W2p, g_W2p);
    float* U1p; cudaGetSymbolAddress((void**)&U1p, g_U1p);

    pack4<<<(256 * 256) / 256, 256>>>(W1p, Vi1, Vf1, Vc1, Vo1, 256);
    pack4<<<(256 * 256) / 256, 256>>>(W2p, Ui2, Uf2, Uc2, Uo2, 256);
    pack4<<<(256 * 256) / 256, 256>>>(W2p + 256 * 1024, Vi2, Vf2, Vc2, Vo2, 256);
    pack4<<<(128 * 256) / 256, 256>>>(U1p, Ui1, Uf1, Uc1, Uo1, 128);
    pack_b<<<1, 256>>>(bi, bf, bc, bo);
    zero_states<<<512, 256>>>();

    // xU = embed @ U1 + b   (M = T*B = 524288)
    xu_gemm<<<dim3(8, 4096), 256>>>(X, C);

    // paired recurrence: t = -1 runs only L0(0); t = 255 runs only L1(255)
    for (int t = -1; t < TT; ++t)
        step_pair<<<256, 256>>>(t);

    out_gemm_mma<<<dim3(NCLASS / 128, BB / 128), 256>>>(Wout, bout, out);
}

// round 7
// speedup vs baseline: 1.2591x; 1.2591x over previous
#include <cuda_runtime.h>
#include <math.h>
#include <stdint.h>

#define BB     2048
#define TT     256
#define EMB    128
#define NH     256
#define NCLASS 32000
#define KB     32

// -------- persistent scratch (static device globals; total ~3.1GB < 4GB bss limit) ----
// g_xS0/g_xS1 hold xU (= embed@U1+b) during phase A, then are OVERWRITTEN with
// xV (= h1@U2+b) by xv_gemm and consumed by phase C.  t<128 -> S0, t>=128 -> S1.
__device__ float g_xS0[(size_t)128 * BB * 1024];
__device__ float g_xS1[(size_t)128 * BB * 1024];
__device__ float g_h1all[(size_t)TT * BB * NH];    // h1(t) for all t (tf32-rounded)
__device__ float g_h2all[(size_t)TT * BB * NH];
__device__ float g_hzero[BB * NH];                 // stays zero (never written)
__device__ float g_W1p[256 * 1024];                // packed V*1 [k][4n+g] tf32
__device__ float g_W2vp[256 * 1024];               // packed V*2
__device__ float g_U2p[256 * 1024];                // packed U*2 (for xv_gemm)
__device__ float g_U1p[128 * 1024];                // packed U*1 (for xu_gemm)
__device__ float g_bp[1024];                       // packed biases
__device__ int   g_bar[32];                        // [layer][16] row-group barriers

// -------- helpers --------
__device__ __forceinline__ uint32_t f2tf(float x) {
    uint32_t r; asm("cvt.rna.tf32.f32 %0, %1;" : "=r"(r) : "f"(x)); return r;
}
__device__ __forceinline__ float sigf(float x) { return 1.f / (1.f + __expf(-x)); }
__device__ __forceinline__ float tanhfa(float x) { return 2.f / (1.f + __expf(-2.f * x)) - 1.f; }

__device__ __forceinline__ void mma_tf32(float c[4], const uint32_t a[4], const uint32_t b[2]) {
    asm volatile(
        "mma.sync.aligned.m16n8k8.row.col.f32.tf32.tf32.f32 "
        "{%0,%1,%2,%3}, {%4,%5,%6,%7}, {%8,%9}, {%0,%1,%2,%3};\n"
        : "+f"(c[0]), "+f"(c[1]), "+f"(c[2]), "+f"(c[3])
        : "r"(a[0]), "r"(a[1]), "r"(a[2]), "r"(a[3]), "r"(b[0]), "r"(b[1]));
}

// -------- weight packing: dst[k][4n+g] = tf32(src_g[k][n]) --------
__global__ void pack4(float* dst, const float* s0, const float* s1,
                      const float* s2, const float* s3, int K) {
    int i = blockIdx.x * blockDim.x + threadIdx.x;
    if (i < K * 256) {
        int base = (i >> 8) * 1024 + ((i & 255) << 2);
        dst[base + 0] = __uint_as_float(f2tf(s0[i]));
        dst[base + 1] = __uint_as_float(f2tf(s1[i]));
        dst[base + 2] = __uint_as_float(f2tf(s2[i]));
        dst[base + 3] = __uint_as_float(f2tf(s3[i]));
    }
}

// U1p pack + bias pack + barrier zero, fused
__global__ void setup_misc(const float* Ui1, const float* Uf1,
                           const float* Uc1, const float* Uo1,
                           const float* bi, const float* bf,
                           const float* bc, const float* bo) {
    int b = blockIdx.x, tid = threadIdx.x;
    if (b < 128) {
        int i = b * 256 + tid;       // 32768 = 128k x 256u
        int base = (i >> 8) * 1024 + ((i & 255) << 2);
        g_U1p[base + 0] = __uint_as_float(f2tf(Ui1[i]));
        g_U1p[base + 1] = __uint_as_float(f2tf(Uf1[i]));
        g_U1p[base + 2] = __uint_as_float(f2tf(Uc1[i]));
        g_U1p[base + 3] = __uint_as_float(f2tf(Uo1[i]));
    } else {
        g_bp[4 * tid + 0] = bi[tid];
        g_bp[4 * tid + 1] = bf[tid];
        g_bp[4 * tid + 2] = bc[tid];
        g_bp[4 * tid + 3] = bo[tid];
        if (tid < 32) g_bar[tid] = 0;
    }
}

// ==========================================================================
// xU precompute: xS[t*2048+b][c] = tf32(C[X[b][t]]) @ U1p + bp.  K=128.
// ==========================================================================
__global__ __launch_bounds__(256) void xu_gemm(const int* __restrict__ X,
                                               const float* __restrict__ C) {
    __shared__ float sA[KB][136];
    __shared__ float sB[KB][136];
    const int tid = threadIdx.x;
    const int warp = tid >> 5, lane = tid & 31;
    const int gid = lane >> 2, tig = lane & 3;
    const int wR = warp >> 2, wC = warp & 3;
    const int mBase = blockIdx.y * 128;
    const int nBase = blockIdx.x * 128;

    const int arow = tid >> 1;
    const int r_glob = mBase + arow;
    const int t_idx = r_glob >> 11, b_idx = r_glob & 2047;
    const int tok = X[b_idx * TT + t_idx];
    const float* Arow = C + (size_t)tok * EMB;
    const int kq0 = (tid & 1) * 4;

    float acc[4][4][4];
#pragma unroll
    for (int mt = 0; mt < 4; ++mt)
#pragma unroll
        for (int nt = 0; nt < 4; ++nt)
#pragma unroll
            for (int q = 0; q < 4; ++q) acc[mt][nt][q] = 0.f;

    float4 pa[4], pb[4];
#pragma unroll
    for (int i = 0; i < 4; ++i)
        pa[i] = *(const float4*)&Arow[(kq0 + i) * 4];
#pragma unroll
    for (int i = 0; i < 4; ++i) {
        int id = tid * 4 + i; int k = id >> 5, n4 = (id & 31) * 4;
        pb[i] = *(const float4*)&g_U1p[(size_t)k * 1024 + nBase + n4];
    }

#pragma unroll 1
    for (int kb = 0; kb < EMB; kb += KB) {
#pragma unroll
        for (int i = 0; i < 4; ++i) {
            int kk = (kq0 + i) * 4;
            sA[kk + 0][arow] = __uint_as_float(f2tf(pa[i].x));
            sA[kk + 1][arow] = __uint_as_float(f2tf(pa[i].y));
            sA[kk + 2][arow] = __uint_as_float(f2tf(pa[i].z));
            sA[kk + 3][arow] = __uint_as_float(f2tf(pa[i].w));
        }
#pragma unroll
        for (int i = 0; i < 4; ++i) {
            int id = tid * 4 + i; int k = id >> 5, n4 = (id & 31) * 4;
            *(float4*)&sB[k][n4] = pb[i];
        }
        __syncthreads();
        if (kb + KB < EMB) {
#pragma unroll
            for (int i = 0; i < 4; ++i)
                pa[i] = *(const float4*)&Arow[kb + KB + (kq0 + i) * 4];
#pragma unroll
            for (int i = 0; i < 4; ++i) {
                int id = tid * 4 + i; int k = id >> 5, n4 = (id & 31) * 4;
                pb[i] = *(const float4*)&g_U1p[(size_t)(kb + KB + k) * 1024 + nBase + n4];
            }
        }
#pragma unroll
        for (int k8 = 0; k8 < KB; k8 += 8) {
            uint32_t af[4][4], bf_[4][2];
#pragma unroll
            for (int mt = 0; mt < 4; ++mt) {
                int r = wR * 64 + mt * 16 + gid;
                af[mt][0] = __float_as_uint(sA[k8 + tig][r]);
                af[mt][1] = __float_as_uint(sA[k8 + tig][r + 8]);
                af[mt][2] = __float_as_uint(sA[k8 + tig + 4][r]);
                af[mt][3] = __float_as_uint(sA[k8 + tig + 4][r + 8]);
            }
#pragma unroll
            for (int nt = 0; nt < 4; ++nt) {
                int c = wC * 32 + nt * 8 + gid;
                bf_[nt][0] = __float_as_uint(sB[k8 + tig][c]);
                bf_[nt][1] = __float_as_uint(sB[k8 + tig + 4][c]);
            }
#pragma unroll
            for (int mt = 0; mt < 4; ++mt)
#pragma unroll
                for (int nt = 0; nt < 4; ++nt)
                    mma_tf32(acc[mt][nt], af[mt], bf_[nt]);
        }
        __syncthreads();
    }

    const int t_tile = mBase >> 11;
    float* xu = (t_tile < 128) ? g_xS0 : g_xS1;
    const size_t rowoff = (size_t)(mBase & ((128 << 11) - 1));
#pragma unroll
    for (int nt = 0; nt < 4; ++nt) {
        int c0 = nBase + wC * 32 + nt * 8 + 2 * tig;
        float2 bb = *(const float2*)&g_bp[c0];
#pragma unroll
        for (int mt = 0; mt < 4; ++mt) {
            int r0 = wR * 64 + mt * 16 + gid;
            float2 v0 = make_float2(acc[mt][nt][0] + bb.x, acc[mt][nt][1] + bb.y);
            float2 v1 = make_float2(acc[mt][nt][2] + bb.x, acc[mt][nt][3] + bb.y);
            *(float2*)&xu[(rowoff + r0) * 1024 + c0] = v0;
            *(float2*)&xu[(rowoff + r0 + 8) * 1024 + c0] = v1;
        }
    }
}

// ==========================================================================
// xV precompute: xS[t*2048+b][c] = h1all[t][b] @ U2p + bp.  K=256.
// Overwrites g_xS0/g_xS1 (xU fully consumed by phase A).
// ==========================================================================
__global__ __launch_bounds__(256) void xv_gemm() {
    __shared__ float sA[KB][136];
    __shared__ float sB[KB][136];
    const int tid = threadIdx.x;
    const int warp = tid >> 5, lane = tid & 31;
    const int gid = lane >> 2, tig = lane & 3;
    const int wR = warp >> 2, wC = warp & 3;
    const int mBase = blockIdx.y * 128;
    const int nBase = blockIdx.x * 128;

    const int arow = tid >> 1;
    const float* Arow = g_h1all + (size_t)(mBase + arow) * NH;
    const int kq0 = (tid & 1) * 4;

    float acc[4][4][4];
#pragma unroll
    for (int mt = 0; mt < 4; ++mt)
#pragma unroll
        for (int nt = 0; nt < 4; ++nt)
#pragma unroll
            for (int q = 0; q < 4; ++q) acc[mt][nt][q] = 0.f;

    float4 pa[4], pb[4];
#pragma unroll
    for (int i = 0; i < 4; ++i)
        pa[i] = *(const float4*)&Arow[(kq0 + i) * 4];
#pragma unroll
    for (int i = 0; i < 4; ++i) {
        int id = tid * 4 + i; int k = id >> 5, n4 = (id & 31) * 4;
        pb[i] = *(const float4*)&g_U2p[(size_t)k * 1024 + nBase + n4];
    }

#pragma unroll 1
    for (int kb = 0; kb < NH; kb += KB) {
#pragma unroll
        for (int i = 0; i < 4; ++i) {
            int kk = (kq0 + i) * 4;
            sA[kk + 0][arow] = pa[i].x;   // h already tf32-rounded
            sA[kk + 1][arow] = pa[i].y;
            sA[kk + 2][arow] = pa[i].z;
            sA[kk + 3][arow] = pa[i].w;
        }
#pragma unroll
        for (int i = 0; i < 4; ++i) {
            int id = tid * 4 + i; int k = id >> 5, n4 = (id & 31) * 4;
            *(float4*)&sB[k][n4] = pb[i];
        }
        __syncthreads();
        if (kb + KB < NH) {
#pragma unroll
            for (int i = 0; i < 4; ++i)
                pa[i] = *(const float4*)&Arow[kb + KB + (kq0 + i) * 4];
#pragma unroll
            for (int i = 0; i < 4; ++i) {
                int id = tid * 4 + i; int k = id >> 5, n4 = (id & 31) * 4;
                pb[i] = *(const float4*)&g_U2p[(size_t)(kb + KB + k) * 1024 + nBase + n4];
            }
        }
#pragma unroll
        for (int k8 = 0; k8 < KB; k8 += 8) {
            uint32_t af[4][4], bf_[4][2];
#pragma unroll
            for (int mt = 0; mt < 4; ++mt) {
                int r = wR * 64 + mt * 16 + gid;
                af[mt][0] = __float_as_uint(sA[k8 + tig][r]);
                af[mt][1] = __float_as_uint(sA[k8 + tig][r + 8]);
                af[mt][2] = __float_as_uint(sA[k8 + tig + 4][r]);
                af[mt][3] = __float_as_uint(sA[k8 + tig + 4][r + 8]);
            }
#pragma unroll
            for (int nt = 0; nt < 4; ++nt) {
                int c = wC * 32 + nt * 8 + gid;
                bf_[nt][0] = __float_as_uint(sB[k8 + tig][c]);
                bf_[nt][1] = __float_as_uint(sB[k8 + tig + 4][c]);
            }
#pragma unroll
            for (int mt = 0; mt < 4; ++mt)
#pragma unroll
                for (int nt = 0; nt < 4; ++nt)
                    mma_tf32(acc[mt][nt], af[mt], bf_[nt]);
        }
        __syncthreads();
    }

    const int t_tile = mBase >> 11;
    float* xv = (t_tile < 128) ? g_xS0 : g_xS1;
    const size_t rowoff = (size_t)(mBase & ((128 << 11) - 1));
#pragma unroll
    for (int nt = 0; nt < 4; ++nt) {
        int c0 = nBase + wC * 32 + nt * 8 + 2 * tig;
        float2 bb = *(const float2*)&g_bp[c0];
#pragma unroll
        for (int mt = 0; mt < 4; ++mt) {
            int r0 = wR * 64 + mt * 16 + gid;
            float2 v0 = make_float2(acc[mt][nt][0] + bb.x, acc[mt][nt][1] + bb.y);
            float2 v1 = make_float2(acc[mt][nt][2] + bb.x, acc[mt][nt][3] + bb.y);
            *(float2*)&xv[(rowoff + r0) * 1024 + c0] = v0;
            *(float2*)&xv[(rowoff + r0 + 8) * 1024 + c0] = v1;
        }
    }
}

// ==========================================================================
// Persistent LSTM phase: 128 CTAs, weights SMEM-resident, 256 steps in one
// launch, per-row-group (8 CTA) atomic barrier between steps, c in registers.
//   layer 0: gates(t) = xS[t] + h1(t-1)@V1  -> h1all[t]
//   layer 1: gates(t) = xS[t] + h2(t-1)@V2  -> h2all[t]
// ==========================================================================
#define PH_SMEM (256*136*4 + 2*64*136*4)   // 208896 B

__global__ __launch_bounds__(256) void lstm_phase(int layer) {
    extern __shared__ float sm[];
    float* sW  = sm;                    // [256][136]
    float* sA0 = sm + 256 * 136;        // [64][136]; reused as sH [32][137]
    float* sA1 = sA0 + 64 * 136;

    const int tid = threadIdx.x;
    const int w = tid >> 5, l = tid & 31;
    const int gid = l >> 2, tig = l & 3;
    const int wR = w >> 2, wC = w & 3;
    const int mg = blockIdx.x >> 3, ng = blockIdx.x & 7;
    const int mBase = mg << 7, nBase = ng << 7;
    const int ubase = nBase >> 2;

    const float* Wsrc = layer ? g_W2vp : g_W1p;
    float* hall = layer ? g_h2all : g_h1all;
    int* bar = g_bar + (layer ? 16 : 0);

    const int sr = (w & 3) * 32 + l;    // staging row 0..127
    const int sf = (w >> 2) * 8;        // float4 base within 64-k chunk

    // load weight tile into SMEM once
#pragma unroll 1
    for (int i = 0; i < 32; ++i) {
        int q = tid + i * 256;
        int k = q >> 5, c4 = q & 31;
        float4 v = *(const float4*)&Wsrc[(size_t)k * 1024 + nBase + c4 * 4];
        *(float4*)&sW[k * 136 + c4 * 4] = v;
    }

    float creg[4][4];
#pragma unroll
    for (int a = 0; a < 4; ++a)
#pragma unroll
        for (int b = 0; b < 4; ++b) creg[a][b] = 0.f;

    __syncthreads();

#pragma unroll 1
    for (int t = 0; t < TT; ++t) {
        if (t > 0) {
            if (tid == 0) {
                int target = t << 3;
                while (atomicAdd(&bar[mg], 0) < target) __nanosleep(40);
            }
            __syncthreads();
            __threadfence();   // acquire: order h loads after counter observation
        }
        const float* Aprev = (t == 0) ? g_hzero : hall + (size_t)(t - 1) * BB * NH;
        const float* xs = (t < 128) ? g_xS0 : g_xS1;
        const float* xrow = xs + (size_t)(t & 127) * BB * 1024;

        float4 pa[8];
#pragma unroll
        for (int j = 0; j < 8; ++j)
            pa[j] = *(const float4*)&Aprev[(size_t)(mBase + sr) * NH + (sf + j) * 4];

        float acc[4][4][4];
#pragma unroll
        for (int mt = 0; mt < 4; ++mt)
#pragma unroll
            for (int nt = 0; nt < 4; ++nt)
#pragma unroll
                for (int q = 0; q < 4; ++q) acc[mt][nt][q] = 0.f;

#pragma unroll
        for (int ck = 0; ck < 4; ++ck) {
            float* sAc = (ck & 1) ? sA1 : sA0;
#pragma unroll
            for (int j = 0; j < 8; ++j) {
                int f4 = (sf + j) * 4;
                sAc[(f4 + 0) * 136 + sr] = pa[j].x;
                sAc[(f4 + 1) * 136 + sr] = pa[j].y;
                sAc[(f4 + 2) * 136 + sr] = pa[j].z;
                sAc[(f4 + 3) * 136 + sr] = pa[j].w;
            }
            __syncthreads();
            if (ck < 3) {
#pragma unroll
                for (int j = 0; j < 8; ++j)
                    pa[j] = *(const float4*)&Aprev[(size_t)(mBase + sr) * NH +
                                                   (ck + 1) * 64 + (sf + j) * 4];
            }
#pragma unroll
            for (int k8 = 0; k8 < 8; ++k8) {
                uint32_t af[4][4], bf_[4][2];
                const int kA = k8 * 8 + tig;
                const int kW = ck * 64 + k8 * 8 + tig;
#pragma unroll
                for (int mt = 0; mt < 4; ++mt) {
                    int r = wR * 64 + mt * 16 + gid;
                    af[mt][0] = __float_as_uint(sAc[kA * 136 + r]);
                    af[mt][1] = __float_as_uint(sAc[kA * 136 + r + 8]);
                    af[mt][2] = __float_as_uint(sAc[(kA + 4) * 136 + r]);
                    af[mt][3] = __float_as_uint(sAc[(kA + 4) * 136 + r + 8]);
                }
#pragma unroll
                for (int nt = 0; nt < 4; ++nt) {
                    int c = wC * 32 + nt * 8 + gid;
                    bf_[nt][0] = __float_as_uint(sW[kW * 136 + c]);
                    bf_[nt][1] = __float_as_uint(sW[(kW + 4) * 136 + c]);
                }
#pragma unroll
                for (int mt = 0; mt < 4; ++mt)
#pragma unroll
                    for (int nt = 0; nt < 4; ++nt)
                        mma_tf32(acc[mt][nt], af[mt], bf_[nt]);
            }
        }

        // ---- epilogue: cell update; h -> sH (transpose) -> coalesced GMEM ----
        float* sH = sA0;      // [32 units][137]
        const bool tlow = ((tig & 1) == 0);
#pragma unroll
        for (int nt = 0; nt < 4; ++nt) {
            int c0 = nBase + wC * 32 + nt * 8 + 2 * tig;
            int n = c0 >> 2;
            int nl = n - ubase;
#pragma unroll
            for (int mt = 0; mt < 4; ++mt) {
                float q0 = acc[mt][nt][0], q1 = acc[mt][nt][1];
                float q2 = acc[mt][nt][2], q3 = acc[mt][nt][3];
                float x0 = tlow ? q2 : q0;
                float x1 = tlow ? q3 : q1;
                float y0 = __shfl_xor_sync(0xffffffffu, x0, 1);
                float y1 = __shfl_xor_sync(0xffffffffu, x1, 1);
                float gI, gF, gG, gO; int rl;
                if (tlow) { gI = q0; gF = q1; gG = y0; gO = y1; rl = wR * 64 + mt * 16 + gid; }
                else      { gI = y0; gF = y1; gG = q2; gO = q3; rl = wR * 64 + mt * 16 + gid + 8; }
                float4 x4 = *(const float4*)&xrow[(size_t)(mBase + rl) * 1024 + (n << 2)];
                float si = sigf(gI + x4.x);
                float sg_f = sigf(gF + x4.y);
                float sg_g = tanhfa(gG + x4.z);
                float sg_o = sigf(gO + x4.w);
                float cn = creg[nt][mt] * sg_f + si * sg_g;
                creg[nt][mt] = cn;
                sH[nl * 137 + rl] = __uint_as_float(f2tf(sg_o * tanhfa(cn)));
            }
        }
        __syncthreads();

        float* hdst = hall + (size_t)t * BB * NH;
#pragma unroll
        for (int i = 0; i < 16; ++i) {
            int q = tid + i * 256;            // 0..4095 = 128 rows x 32 units
            int u = q & 31, r = q >> 5;
            hdst[(size_t)(mBase + r) * NH + ubase + u] = sH[u * 137 + r];
        }
        __threadfence();
        __syncthreads();
        if (tid == 0) atomicAdd(&bar[mg], 1);
    }
}

// ==========================================================================
// Output GEMM: out = h2(255) @ W_out + b_out
// ==========================================================================
__global__ __launch_bounds__(256) void out_gemm_mma(const float* __restrict__ Wout,
                                                    const float* __restrict__ bout,
                                                    float* __restrict__ out) {
    __shared__ float sA[KB][136];
    __shared__ float sB[KB][136];
    const int tid = threadIdx.x;
    const int warp = tid >> 5, lane = tid & 31;
    const int gid = lane >> 2, tig = lane & 3;
    const int wR = warp >> 2, wC = warp & 3;
    const int mBase = blockIdx.y * 128;
    const int nBase = blockIdx.x * 128;
    const float* h2 = g_h2all + (size_t)(TT - 1) * BB * NH;

    float acc[4][4][4];
#pragma unroll
    for (int mt = 0; mt < 4; ++mt)
#pragma unroll
        for (int nt = 0; nt < 4; ++nt)
#pragma unroll
            for (int q = 0; q < 4; ++q) acc[mt][nt][q] = 0.f;

    const int arow = tid >> 1;
    const int kq0 = (tid & 1) * 4;

    float4 pa[4], pb[4];
#pragma unroll
    for (int i = 0; i < 4; ++i)
        pa[i] = *(const float4*)&h2[(size_t)(mBase + arow) * NH + (kq0 + i) * 4];
#pragma unroll
    for (int i = 0; i < 4; ++i) {
        int id = tid * 4 + i; int k = id >> 5, n4 = (id & 31) * 4;
        pb[i] = *(const float4*)&Wout[(size_t)k * NCLASS + nBase + n4];
    }

#pragma unroll 1
    for (int kb = 0; kb < NH; kb += KB) {
#pragma unroll
        for (int i = 0; i < 4; ++i) {
            int kk = (kq0 + i) * 4;
            sA[kk + 0][arow] = pa[i].x;    // h pre-rounded
            sA[kk + 1][arow] = pa[i].y;
            sA[kk + 2][arow] = pa[i].z;
            sA[kk + 3][arow] = pa[i].w;
        }
#pragma unroll
        for (int i = 0; i < 4; ++i) {
            int id = tid * 4 + i; int k = id >> 5, n4 = (id & 31) * 4;
            float4 v = pb[i];
            v.x = __uint_as_float(f2tf(v.x)); v.y = __uint_as_float(f2tf(v.y));
            v.z = __uint_as_float(f2tf(v.z)); v.w = __uint_as_float(f2tf(v.w));
            *(float4*)&sB[k][n4] = v;
        }
        __syncthreads();
        if (kb + KB < NH) {
#pragma unroll
            for (int i = 0; i < 4; ++i)
                pa[i] = *(const float4*)&h2[(size_t)(mBase + arow) * NH + kb + KB + (kq0 + i) * 4];
#pragma unroll
            for (int i = 0; i < 4; ++i) {
                int id = tid * 4 + i; int k = id >> 5, n4 = (id & 31) * 4;
                pb[i] = *(const float4*)&Wout[(size_t)(kb + KB + k) * NCLASS + nBase + n4];
            }
        }
#pragma unroll
        for (int k8 = 0; k8 < KB; k8 += 8) {
            uint32_t af[4][4], bf_[4][2];
#pragma unroll
            for (int mt = 0; mt < 4; ++mt) {
                int r = wR * 64 + mt * 16 + gid;
                af[mt][0] = __float_as_uint(sA[k8 + tig][r]);
                af[mt][1] = __float_as_uint(sA[k8 + tig][r + 8]);
                af[mt][2] = __float_as_uint(sA[k8 + tig + 4][r]);
                af[mt][3] = __float_as_uint(sA[k8 + tig + 4][r + 8]);
            }
#pragma unroll
            for (int nt = 0; nt < 4; ++nt) {
                int c = wC * 32 + nt * 8 + gid;
                bf_[nt][0] = __float_as_uint(sB[k8 + tig][c]);
                bf_[nt][1] = __float_as_uint(sB[k8 + tig + 4][c]);
            }
#pragma unroll
            for (int mt = 0; mt < 4; ++mt)
#pragma unroll
                for (int nt = 0; nt < 4; ++nt)
                    mma_tf32(acc[mt][nt], af[mt], bf_[nt]);
        }
        __syncthreads();
    }

#pragma unroll
    for (int nt = 0; nt < 4; ++nt) {
        int c0 = nBase + wC * 32 + nt * 8 + 2 * tig;
        float2 bb = *(const float2*)&bout[c0];
#pragma unroll
        for (int mt = 0; mt < 4; ++mt) {
            int r0 = mBase + wR * 64 + mt * 16 + gid;
            float2 v0 = make_float2(acc[mt][nt][0] + bb.x, acc[mt][nt][1] + bb.y);
            float2 v1 = make_float2(acc[mt][nt][2] + bb.x, acc[mt][nt][3] + bb.y);
            *(float2*)&out[(size_t)r0 * NCLASS + c0] = v0;
            *(float2*)&out[(size_t)(r0 + 8) * NCLASS + c0] = v1;
        }
    }
}

// -------- launch --------
extern "C" void kernel_launch(void* const* d_in, const int* in_sizes, int n_in,
                              void* d_out, int out_size) {
    (void)in_sizes; (void)n_in; (void)out_size;
    const int*   X    = (const int*)d_in[0];
    const float* C    = (const float*)d_in[1];
    const float* Ui1  = (const float*)d_in[2];
    const float* Vi1  = (const float*)d_in[3];
    const float* Ui2  = (const float*)d_in[4];
    const float* Vi2  = (const float*)d_in[5];
    const float* bi   = (const float*)d_in[6];
    const float* Uf1  = (const float*)d_in[7];
    const float* Vf1  = (const float*)d_in[8];
    const float* Uf2  = (const float*)d_in[9];
    const float* Vf2  = (const float*)d_in[10];
    const float* bf   = (const float*)d_in[11];
    const float* Uc1  = (const float*)d_in[12];
    const float* Vc1  = (const float*)d_in[13];
    const float* Uc2  = (const float*)d_in[14];
    const float* Vc2  = (const float*)d_in[15];
    const float* bc   = (const float*)d_in[16];
    const float* Uo1  = (const float*)d_in[17];
    const float* Vo1  = (const float*)d_in[18];
    const float* Uo2  = (const float*)d_in[19];
    const float* Vo2  = (const float*)d_in[20];
    const float* bo   = (const float*)d_in[21];
    const float* Wout = (const float*)d_in[22];
    const float* bout = (const float*)d_in[23];
    float* out = (float*)d_out;

    float* W1p;  cudaGetSymbolAddress((void**)&W1p,  g_W1p);
    float* W2vp; cudaGetSymbolAddress((void**)&W2vp, g_W2vp);
    float* U2p;  cudaGetSymbolAddress((void**)&U2p,  g_U2p);

    cudaFuncSetAttribute(lstm_phase, cudaFuncAttributeMaxDynamicSharedMemorySize, PH_SMEM);

    // launches 1-4: packing/setup
    pack4<<<256, 256>>>(W1p,  Vi1, Vf1, Vc1, Vo1, 256);
    pack4<<<256, 256>>>(W2vp, Vi2, Vf2, Vc2, Vo2, 256);
    pack4<<<256, 256>>>(U2p,  Ui2, Uf2, Uc2, Uo2, 256);
    setup_misc<<<129, 256>>>(Ui1, Uf1, Uc1, Uo1, bi, bf, bc, bo);

    // launch 5: xU = embed @ U1 + b  (writes g_xS)
    xu_gemm<<<dim3(8, 4096), 256>>>(X, C);

    // launch 6: phase A (layer-1 recurrence, all 256 steps)  [ncu -s 5 lands here]
    lstm_phase<<<128, 256, PH_SMEM>>>(0);

    // launch 7: xV = h1all @ U2 + b  (overwrites g_xS)
    xv_gemm<<<dim3(8, 4096), 256>>>();

    // launch 8: phase C (layer-2 recurrence)
    lstm_phase<<<128, 256, PH_SMEM>>>(1);

    // launch 9: output projection
    out_gemm_mma<<<dim3(NCLASS / 128, BB / 128), 256>>>(Wout, bout, out);
}

// round 10
// speedup vs baseline: 2.1616x; 1.7168x over previous
#include <cuda_runtime.h>
#include <cuda_fp16.h>
#include <math.h>
#include <stdint.h>

#define BB     2048
#define TT     256
#define EMB    128
#define NH     256
#define NCLASS 32000

// -------- persistent scratch (~2.6GB total, under 4GB bss relocation limit) ----
__device__ float  g_xS0[(size_t)128 * BB * 1024];   // xU fp32 (incl bias), t<128
__device__ float  g_xS1[(size_t)128 * BB * 1024];   // t>=128
__device__ __half g_h1h[(size_t)TT * BB * NH];      // h1(t) history, fp16
__device__ __half g_h2h[(size_t)TT * BB * NH];      // h2(t) history, fp16
__device__ __half g_hzh[BB * NH];                   // zeros (never written)
__device__ unsigned g_W1h[128 * 1024];              // V*1  half2[k2][1024]
__device__ unsigned g_W2h[256 * 1024];              // [U*2;V*2] half2[k2][1024]
__device__ unsigned g_U1h[64 * 1024];               // U*1  half2[k2][1024]
__device__ unsigned g_Wouth[128 * 32000];           // W_out half2[k2][32000]
__device__ float  g_bp[1024];                       // packed biases fp32
__device__ int    g_bar[32];                        // [layer][16] barriers

// -------- helpers --------
__device__ __forceinline__ float sigf(float x) { return 1.f / (1.f + __expf(-x)); }
__device__ __forceinline__ float tanhfa(float x) { return 2.f / (1.f + __expf(-2.f * x)) - 1.f; }

__device__ __forceinline__ unsigned h2u(__half2 h) {
    return *reinterpret_cast<unsigned*>(&h);
}

__device__ __forceinline__ void mma_f16(float c[4], unsigned a0, unsigned a1,
                                        unsigned a2, unsigned a3,
                                        unsigned b0, unsigned b1) {
    asm volatile(
        "mma.sync.aligned.m16n8k16.row.col.f32.f16.f16.f32 "
        "{%0,%1,%2,%3}, {%4,%5,%6,%7}, {%8,%9}, {%0,%1,%2,%3};\n"
        : "+f"(c[0]), "+f"(c[1]), "+f"(c[2]), "+f"(c[3])
        : "r"(a0), "r"(a1), "r"(a2), "r"(a3), "r"(b0), "r"(b1));
}

// -------- packing: dst half[(k2*1024+4u+g)*2 + (k&1)] = f16(src_g[k][u]) ------
__global__ void pack4h(unsigned* dst, const float* s0, const float* s1,
                       const float* s2, const float* s3, int koff) {
    int i = blockIdx.x * blockDim.x + threadIdx.x;   // over 256k x 256u
    int k = i >> 8, u = i & 255;
    __half* d = (__half*)dst;
    int kk = k + koff;
    size_t base = ((size_t)(kk >> 1) * 1024 + 4 * u) * 2 + (kk & 1);
    d[base + 0] = __float2half(s0[k * 256 + u]);
    d[base + 2] = __float2half(s1[k * 256 + u]);
    d[base + 4] = __float2half(s2[k * 256 + u]);
    d[base + 6] = __float2half(s3[k * 256 + u]);
}

__global__ void packWout(const float* __restrict__ Wout) {
    int n = blockIdx.x * blockDim.x + threadIdx.x;   // 0..31999
    int k = blockIdx.y;                              // 0..255
    if (n < NCLASS) {
        ((__half*)g_Wouth)[((size_t)(k >> 1) * NCLASS + n) * 2 + (k & 1)] =
            __float2half(Wout[(size_t)k * NCLASS + n]);
    }
}

// U1h pack + bias pack + barrier zero
__global__ void pack_misc(const float* Ui1, const float* Uf1,
                          const float* Uc1, const float* Uo1,
                          const float* bi, const float* bf,
                          const float* bc, const float* bo) {
    int b = blockIdx.x, tid = threadIdx.x;
    if (b < 128) {
        int k = b, u = tid;
        __half* d = (__half*)g_U1h;
        size_t base = ((size_t)(k >> 1) * 1024 + 4 * u) * 2 + (k & 1);
        d[base + 0] = __float2half(Ui1[k * 256 + u]);
        d[base + 2] = __float2half(Uf1[k * 256 + u]);
        d[base + 4] = __float2half(Uc1[k * 256 + u]);
        d[base + 6] = __float2half(Uo1[k * 256 + u]);
    } else {
        g_bp[4 * tid + 0] = bi[tid];
        g_bp[4 * tid + 1] = bf[tid];
        g_bp[4 * tid + 2] = bc[tid];
        g_bp[4 * tid + 3] = bo[tid];
        if (tid < 32) g_bar[tid] = 0;
    }
}

// ==========================================================================
// xU: xS[t*2048+b][c] = f16(C[X[b][t]]) @ U1h + bp.  M=524288, N=1024, K=128.
// CTA 128x128, fp16 mma.  smem: sW[64][132] + sA[128][68] (dynamic, 68608B)
// ==========================================================================
#define XU_SMEM 68608
__global__ __launch_bounds__(256) void xu_gemm(const int* __restrict__ X,
                                               const float* __restrict__ C) {
    extern __shared__ unsigned sm_xu[];
    unsigned* sw = sm_xu;            // [k2<64][132]
    unsigned* sa = sm_xu + 64 * 132; // [row<128][68]
    const int tid = threadIdx.x;
    const int w = tid >> 5, l = tid & 31;
    const int gid = l >> 2, tig = l & 3;
    const int wR = w >> 2, wC = w & 3;
    const int mBase = blockIdx.y * 128;
    const int nBase = blockIdx.x * 128;

    // stage W (64 k2 x 128 cols)
#pragma unroll
    for (int i = 0; i < 8; ++i) {
        int q = tid + i * 256;             // 2048 = 64*32
        int k2 = q >> 5, c4 = q & 31;
        *(uint4*)&sw[k2 * 132 + c4 * 4] = *(const uint4*)&g_U1h[k2 * 1024 + nBase + c4 * 4];
    }
    // stage A: gather token row, cvt fp32->fp16
    {
        int r = tid >> 1, part = tid & 1;
        int r_glob = mBase + r;
        int t_idx = r_glob >> 11, b_idx = r_glob & 2047;
        int tok = X[b_idx * TT + t_idx];
        const float* src = C + (size_t)tok * EMB + part * 64;
#pragma unroll
        for (int j = 0; j < 8; ++j) {
            float4 v0 = *(const float4*)&src[j * 8];
            float4 v1 = *(const float4*)&src[j * 8 + 4];
            uint4 o;
            o.x = h2u(__floats2half2_rn(v0.x, v0.y));
            o.y = h2u(__floats2half2_rn(v0.z, v0.w));
            o.z = h2u(__floats2half2_rn(v1.x, v1.y));
            o.w = h2u(__floats2half2_rn(v1.z, v1.w));
            *(uint4*)&sa[r * 68 + part * 32 + j * 4] = o;
        }
    }
    __syncthreads();

    float acc[4][4][4];
#pragma unroll
    for (int mt = 0; mt < 4; ++mt)
#pragma unroll
        for (int nt = 0; nt < 4; ++nt)
#pragma unroll
            for (int q = 0; q < 4; ++q) acc[mt][nt][q] = 0.f;

#pragma unroll
    for (int ki = 0; ki < 8; ++ki) {
        const int kb = ki * 8;
        unsigned bf_[4][2];
#pragma unroll
        for (int nt = 0; nt < 4; ++nt) {
            int c = wC * 32 + nt * 8 + gid;
            bf_[nt][0] = sw[(kb + tig) * 132 + c];
            bf_[nt][1] = sw[(kb + 4 + tig) * 132 + c];
        }
#pragma unroll
        for (int mt = 0; mt < 4; ++mt) {
            int r = wR * 64 + mt * 16 + gid;
            unsigned a0 = sa[r * 68 + kb + tig];
            unsigned a1 = sa[(r + 8) * 68 + kb + tig];
            unsigned a2 = sa[r * 68 + kb + 4 + tig];
            unsigned a3 = sa[(r + 8) * 68 + kb + 4 + tig];
#pragma unroll
            for (int nt = 0; nt < 4; ++nt)
                mma_f16(acc[mt][nt], a0, a1, a2, a3, bf_[nt][0], bf_[nt][1]);
        }
    }

    const int t_tile = mBase >> 11;
    float* xu = (t_tile < 128) ? g_xS0 : g_xS1;
    const size_t rowoff = (size_t)(mBase & ((128 << 11) - 1));
#pragma unroll
    for (int nt = 0; nt < 4; ++nt) {
        int c0 = nBase + wC * 32 + nt * 8 + 2 * tig;
        float2 bb = *(const float2*)&g_bp[c0];
#pragma unroll
        for (int mt = 0; mt < 4; ++mt) {
            int r0 = wR * 64 + mt * 16 + gid;
            float2 v0 = make_float2(acc[mt][nt][0] + bb.x, acc[mt][nt][1] + bb.y);
            float2 v1 = make_float2(acc[mt][nt][2] + bb.x, acc[mt][nt][3] + bb.y);
            *(float2*)&xu[(rowoff + r0) * 1024 + c0] = v0;
            *(float2*)&xu[(rowoff + r0 + 8) * 1024 + c0] = v1;
        }
    }
}

// ==========================================================================
// Persistent LSTM phase, fp16 MMA, weights SMEM-resident.
//   layer 0: gates(t) = h1(t-1)@V1 + xS[t]           (K=256)
//   layer 1: gates(t) = h1all[t]@U2 + h2(t-1)@V2 + b (K=512, 2 chunks)
// 128 CTAs: 16 row groups x 8 n-slices.  c-state in registers.
// smem: sW[256][132] (135168B) + sA[128][132] (67584B) = 202752B
// ==========================================================================
#define PH_SMEM 202752
__global__ __launch_bounds__(256) void lstm_phase(int layer) {
    extern __shared__ unsigned sm_ph[];
    unsigned* sw = sm_ph;                 // [k2][132]
    unsigned* sa = sm_ph + 256 * 132;     // [row][132]

    const int tid = threadIdx.x;
    const int w = tid >> 5, l = tid & 31;
    const int gid = l >> 2, tig = l & 3;
    const int wR = w >> 2, wC = w & 3;
    const int mg = blockIdx.x >> 3, ng = blockIdx.x & 7;
    const int mBase = mg << 7, nBase = ng << 7;
    const int ubase = ng << 5;

    const unsigned* Wsrc = layer ? g_W2h : g_W1h;
    const int k2tot = layer ? 256 : 128;
    __half* hall = layer ? g_h2h : g_h1h;
    int* bar = g_bar + (layer ? 16 : 0);

    // load weight slice once
    for (int q = tid; q < k2tot * 32; q += 256) {
        int k2 = q >> 5, c4 = q & 31;
        *(uint4*)&sw[k2 * 132 + c4 * 4] = *(const uint4*)&Wsrc[k2 * 1024 + nBase + c4 * 4];
    }

    float creg[4][4];
#pragma unroll
    for (int a = 0; a < 4; ++a)
#pragma unroll
        for (int b = 0; b < 4; ++b) creg[a][b] = 0.f;

    __syncthreads();

#pragma unroll 1
    for (int t = 0; t < TT; ++t) {
        if (t > 0) {
            if (tid == 0) {
                int target = t << 3;
                while (atomicAdd(&bar[mg], 0) < target) __nanosleep(40);
            }
            __syncthreads();
            __threadfence();
        }

        float acc[4][4][4];
#pragma unroll
        for (int mt = 0; mt < 4; ++mt)
#pragma unroll
            for (int nt = 0; nt < 4; ++nt)
#pragma unroll
                for (int q = 0; q < 4; ++q) acc[mt][nt][q] = 0.f;

        const int nchunk = layer ? 2 : 1;
#pragma unroll 1
        for (int ch = 0; ch < nchunk; ++ch) {
            const __half* hsrc;
            if (layer == 0)
                hsrc = (t == 0) ? g_hzh : g_h1h + (size_t)(t - 1) * BB * NH;
            else if (ch == 0)
                hsrc = g_h1h + (size_t)t * BB * NH;
            else
                hsrc = (t == 0) ? g_hzh : g_h2h + (size_t)(t - 1) * BB * NH;
            if (ch) __syncthreads();   // protect sa reuse

            // stage A: 64KB pure copy (fp16, fragment-native layout)
#pragma unroll
            for (int i = 0; i < 16; ++i) {
                int q = tid + i * 256;
                int r = q >> 5, c = q & 31;
                *(uint4*)&sa[r * 132 + c * 4] =
                    *(const uint4*)(hsrc + (size_t)(mBase + r) * NH + c * 8);
            }
            __syncthreads();

            const int kw0 = ch << 7;   // W k2 base for this chunk
#pragma unroll 4
            for (int ki = 0; ki < 16; ++ki) {
                const int kb = ki * 8;
                unsigned bf_[4][2];
#pragma unroll
                for (int nt = 0; nt < 4; ++nt) {
                    int c = wC * 32 + nt * 8 + gid;
                    bf_[nt][0] = sw[(kw0 + kb + tig) * 132 + c];
                    bf_[nt][1] = sw[(kw0 + kb + 4 + tig) * 132 + c];
                }
#pragma unroll
                for (int mt = 0; mt < 4; ++mt) {
                    int r = wR * 64 + mt * 16 + gid;
                    unsigned a0 = sa[r * 132 + kb + tig];
                    unsigned a1 = sa[(r + 8) * 132 + kb + tig];
                    unsigned a2 = sa[r * 132 + kb + 4 + tig];
                    unsigned a3 = sa[(r + 8) * 132 + kb + 4 + tig];
#pragma unroll
                    for (int nt = 0; nt < 4; ++nt)
                        mma_f16(acc[mt][nt], a0, a1, a2, a3, bf_[nt][0], bf_[nt][1]);
                }
            }
        }

        // ---- epilogue: LSTM cell; h(fp16) -> sH -> coalesced GMEM ----
        __syncthreads();                       // all mma reads of sa done
        __half* sH = (__half*)sa;              // [32 units][132]
        const float* xrow = nullptr;
        if (layer == 0) {
            const float* xs = (t < 128) ? g_xS0 : g_xS1;
            xrow = xs + (size_t)(t & 127) * BB * 1024;
        }
        const bool tlow = ((tig & 1) == 0);
#pragma unroll
        for (int nt = 0; nt < 4; ++nt) {
            int c0l = wC * 32 + nt * 8 + 2 * tig;
            int nl = c0l >> 2;
#pragma unroll
            for (int mt = 0; mt < 4; ++mt) {
                float q0 = acc[mt][nt][0], q1 = acc[mt][nt][1];
                float q2 = acc[mt][nt][2], q3 = acc[mt][nt][3];
                float x0 = tlow ? q2 : q0;
                float x1 = tlow ? q3 : q1;
                float y0 = __shfl_xor_sync(0xffffffffu, x0, 1);
                float y1 = __shfl_xor_sync(0xffffffffu, x1, 1);
                float gI, gF, gG, gO; int rl;
                if (tlow) { gI = q0; gF = q1; gG = y0; gO = y1; rl = wR * 64 + mt * 16 + gid; }
                else      { gI = y0; gF = y1; gG = q2; gO = q3; rl = wR * 64 + mt * 16 + gid + 8; }
                float a0, a1, a2, a3;
                if (layer == 0) {
                    float4 x4 = *(const float4*)&xrow[(size_t)(mBase + rl) * 1024 +
                                                      ((ubase + nl) << 2)];
                    a0 = x4.x; a1 = x4.y; a2 = x4.z; a3 = x4.w;
                } else {
                    float4 b4 = *(const float4*)&g_bp[(ubase + nl) << 2];
                    a0 = b4.x; a1 = b4.y; a2 = b4.z; a3 = b4.w;
                }
                float si = sigf(gI + a0);
                float sf = sigf(gF + a1);
                float sg = tanhfa(gG + a2);
                float so = sigf(gO + a3);
                float cn = creg[nt][mt] * sf + si * sg;
                creg[nt][mt] = cn;
                sH[nl * 132 + rl] = __float2half(so * tanhfa(cn));
            }
        }
        __syncthreads();

        __half* hdst = hall + (size_t)t * BB * NH;
#pragma unroll
        for (int i = 0; i < 8; ++i) {
            int q = tid + i * 256;           // 2048 = 128 rows x 16 half2
            int r = q >> 4, u2 = q & 15;
            __half2 hv = __halves2half2(sH[(2 * u2) * 132 + r],
                                        sH[(2 * u2 + 1) * 132 + r]);
            *(__half2*)(hdst + (size_t)(mBase + r) * NH + ubase + 2 * u2) = hv;
        }
        __threadfence();
        __syncthreads();
        if (tid == 0) atomicAdd(&bar[mg], 1);
    }
}

// ==========================================================================
// Output GEMM: out = h2(255) @ W_out + b_out.  fp16 mma.  M=2048,N=32000,K=256
// smem: sW[128][132] + sA[128][132] = 135168B
// ==========================================================================
#define OUT_SMEM 135168
__global__ __launch_bounds__(256) void out_gemm(const float* __restrict__ bout,
                                                float* __restrict__ out) {
    extern __shared__ unsigned sm_o[];
    unsigned* sw = sm_o;
    unsigned* sa = sm_o + 128 * 132;
    const int tid = threadIdx.x;
    const int w = tid >> 5, l = tid & 31;
    const int gid = l >> 2, tig = l & 3;
    const int wR = w >> 2, wC = w & 3;
    const int mBase = blockIdx.y * 128;
    const int nBase = blockIdx.x * 128;
    const __half* h2 = g_h2h + (size_t)(TT - 1) * BB * NH;

    // stage W (128 k2 x 128 cols)
#pragma unroll
    for (int i = 0; i < 16; ++i) {
        int q = tid + i * 256;
        int k2 = q >> 5, c4 = q & 31;
        *(uint4*)&sw[k2 * 132 + c4 * 4] =
            *(const uint4*)&g_Wouth[(size_t)k2 * NCLASS + nBase + c4 * 4];
    }
    // stage A (pure copy of fp16 h2)
#pragma unroll
    for (int i = 0; i < 16; ++i) {
        int q = tid + i * 256;
        int r = q >> 5, c = q & 31;
        *(uint4*)&sa[r * 132 + c * 4] =
            *(const uint4*)(h2 + (size_t)(mBase + r) * NH + c * 8);
    }
    __syncthreads();

    float acc[4][4][4];
#pragma unroll
    for (int mt = 0; mt < 4; ++mt)
#pragma unroll
        for (int nt = 0; nt < 4; ++nt)
#pragma unroll
            for (int q = 0; q < 4; ++q) acc[mt][nt][q] = 0.f;

#pragma unroll 4
    for (int ki = 0; ki < 16; ++ki) {
        const int kb = ki * 8;
        unsigned bf_[4][2];
#pragma unroll
        for (int nt = 0; nt < 4; ++nt) {
            int c = wC * 32 + nt * 8 + gid;
            bf_[nt][0] = sw[(kb + tig) * 132 + c];
            bf_[nt][1] = sw[(kb + 4 + tig) * 132 + c];
        }
#pragma unroll
        for (int mt = 0; mt < 4; ++mt) {
            int r = wR * 64 + mt * 16 + gid;
            unsigned a0 = sa[r * 132 + kb + tig];
            unsigned a1 = sa[(r + 8) * 132 + kb + tig];
            unsigned a2 = sa[r * 132 + kb + 4 + tig];
            unsigned a3 = sa[(r + 8) * 132 + kb + 4 + tig];
#pragma unroll
            for (int nt = 0; nt < 4; ++nt)
                mma_f16(acc[mt][nt], a0, a1, a2, a3, bf_[nt][0], bf_[nt][1]);
        }
    }

#pragma unroll
    for (int nt = 0; nt < 4; ++nt) {
        int c0 = nBase + wC * 32 + nt * 8 + 2 * tig;
        float2 bb = *(const float2*)&bout[c0];
#pragma unroll
        for (int mt = 0; mt < 4; ++mt) {
            int r0 = mBase + wR * 64 + mt * 16 + gid;
            float2 v0 = make_float2(acc[mt][nt][0] + bb.x, acc[mt][nt][1] + bb.y);
            float2 v1 = make_float2(acc[mt][nt][2] + bb.x, acc[mt][nt][3] + bb.y);
            *(float2*)&out[(size_t)r0 * NCLASS + c0] = v0;
            *(float2*)&out[(size_t)(r0 + 8) * NCLASS + c0] = v1;
        }
    }
}

// -------- launch --------
extern "C" void kernel_launch(void* const* d_in, const int* in_sizes, int n_in,
                              void* d_out, int out_size) {
    (void)in_sizes; (void)n_in; (void)out_size;
    const int*   X    = (const int*)d_in[0];
    const float* C    = (const float*)d_in[1];
    const float* Ui1  = (const float*)d_in[2];
    const float* Vi1  = (const float*)d_in[3];
    const float* Ui2  = (const float*)d_in[4];
    const float* Vi2  = (const float*)d_in[5];
    const float* bi   = (const float*)d_in[6];
    const float* Uf1  = (const float*)d_in[7];
    const float* Vf1  = (const float*)d_in[8];
    const float* Uf2  = (const float*)d_in[9];
    const float* Vf2  = (const float*)d_in[10];
    const float* bf   = (const float*)d_in[11];
    const float* Uc1  = (const float*)d_in[12];
    const float* Vc1  = (const float*)d_in[13];
    const float* Uc2  = (const float*)d_in[14];
    const float* Vc2  = (const float*)d_in[15];
    const float* bc   = (const float*)d_in[16];
    const float* Uo1  = (const float*)d_in[17];
    const float* Vo1  = (const float*)d_in[18];
    const float* Uo2  = (const float*)d_in[19];
    const float* Vo2  = (const float*)d_in[20];
    const float* bo   = (const float*)d_in[21];
    const float* Wout = (const float*)d_in[22];
    const float* bout = (const float*)d_in[23];
    float* out = (float*)d_out;

    unsigned* W1h; cudaGetSymbolAddress((void**)&W1h, g_W1h);
    unsigned* W2h; cudaGetSymbolAddress((void**)&W2h, g_W2h);

    cudaFuncSetAttribute(lstm_phase, cudaFuncAttributeMaxDynamicSharedMemorySize, PH_SMEM);
    cudaFuncSetAttribute(xu_gemm,    cudaFuncAttributeMaxDynamicSharedMemorySize, XU_SMEM);
    cudaFuncSetAttribute(out_gemm,   cudaFuncAttributeMaxDynamicSharedMemorySize, OUT_SMEM);

    // packing
    pack4h<<<256, 256>>>(W1h, Vi1, Vf1, Vc1, Vo1, 0);
    pack4h<<<256, 256>>>(W2h, Ui2, Uf2, Uc2, Uo2, 0);
    pack4h<<<256, 256>>>(W2h, Vi2, Vf2, Vc2, Vo2, 256);
    packWout<<<dim3(125, 256), 256>>>(Wout);
    pack_misc<<<129, 256>>>(Ui1, Uf1, Uc1, Uo1, bi, bf, bc, bo);

    // xU = embed @ U1 + b
    xu_gemm<<<dim3(8, 4096), 256, XU_SMEM>>>(X, C);

    // phase A: layer-1 recurrence (256 steps, one launch)
    lstm_phase<<<128, 256, PH_SMEM>>>(0);

    // phase C: layer-2 recurrence (U2-projection folded in, K=512)
    lstm_phase<<<128, 256, PH_SMEM>>>(1);

    // output projection
    out_gemm<<<dim3(NCLASS / 128, BB / 128), 256, OUT_SMEM>>>(bout, out);
}

// round 13
// speedup vs baseline: 2.3267x; 1.0763x over previous
#include <cuda_runtime.h>
#include <cuda_fp16.h>
#include <math.h>
#include <stdint.h>

#define BB     2048
#define TT     256
#define EMB    128
#define NH     256
#define NCLASS 32000

// -------- persistent scratch (~1.6GB total) ----
__device__ __half g_xS0[(size_t)128 * BB * 1024];   // xU fp16 (incl bias), t<128
__device__ __half g_xS1[(size_t)128 * BB * 1024];   // t>=128
__device__ __half g_h1h[(size_t)TT * BB * NH];      // h1(t) history, fp16
__device__ __half g_h2h[(size_t)TT * BB * NH];      // h2(t) history, fp16
__device__ __half g_hzh[BB * NH];                   // zeros (never written)
__device__ unsigned g_W1h[128 * 1024];              // V*1  half2[k2][1024]
__device__ unsigned g_W2h[256 * 1024];              // [U*2;V*2] half2[k2][1024]
__device__ unsigned g_U1h[64 * 1024];               // U*1  half2[k2][1024]
__device__ unsigned g_Wouth[128 * 32000];           // W_out half2[k2][32000]
__device__ float  g_bp[1024];                       // packed biases fp32
__device__ int    g_bar[32];                        // [layer][16] barriers

// -------- helpers --------
__device__ __forceinline__ float sigf(float x) { return 1.f / (1.f + __expf(-x)); }
__device__ __forceinline__ float tanhfa(float x) { return 2.f / (1.f + __expf(-2.f * x)) - 1.f; }

__device__ __forceinline__ unsigned h2u(__half2 h) {
    return *reinterpret_cast<unsigned*>(&h);
}

__device__ __forceinline__ int ld_acquire(int* p) {
    int v;
    asm volatile("ld.acquire.gpu.global.s32 %0, [%1];" : "=r"(v) : "l"(p) : "memory");
    return v;
}
__device__ __forceinline__ void red_release(int* p) {
    asm volatile("red.release.gpu.global.add.s32 [%0], %1;" :: "l"(p), "r"(1) : "memory");
}

__device__ __forceinline__ void mma_f16(float c[4], unsigned a0, unsigned a1,
                                        unsigned a2, unsigned a3,
                                        unsigned b0, unsigned b1) {
    asm volatile(
        "mma.sync.aligned.m16n8k16.row.col.f32.f16.f16.f32 "
        "{%0,%1,%2,%3}, {%4,%5,%6,%7}, {%8,%9}, {%0,%1,%2,%3};\n"
        : "+f"(c[0]), "+f"(c[1]), "+f"(c[2]), "+f"(c[3])
        : "r"(a0), "r"(a1), "r"(a2), "r"(a3), "r"(b0), "r"(b1));
}

// -------- packing (one launch, blockIdx.y selects weight set) --------
__global__ void pack4h_all(const float* Vi1, const float* Vf1, const float* Vc1, const float* Vo1,
                           const float* Ui2, const float* Uf2, const float* Uc2, const float* Uo2,
                           const float* Vi2, const float* Vf2, const float* Vc2, const float* Vo2) {
    int i = blockIdx.x * blockDim.x + threadIdx.x;   // over 256k x 256u
    int set = blockIdx.y;
    const float *s0, *s1, *s2, *s3; unsigned* dst; int koff;
    if (set == 0)      { s0 = Vi1; s1 = Vf1; s2 = Vc1; s3 = Vo1; dst = g_W1h; koff = 0; }
    else if (set == 1) { s0 = Ui2; s1 = Uf2; s2 = Uc2; s3 = Uo2; dst = g_W2h; koff = 0; }
    else               { s0 = Vi2; s1 = Vf2; s2 = Vc2; s3 = Vo2; dst = g_W2h; koff = 256; }
    int k = i >> 8, u = i & 255;
    __half* d = (__half*)dst;
    int kk = k + koff;
    size_t base = ((size_t)(kk >> 1) * 1024 + 4 * u) * 2 + (kk & 1);
    d[base + 0] = __float2half(s0[k * 256 + u]);
    d[base + 2] = __float2half(s1[k * 256 + u]);
    d[base + 4] = __float2half(s2[k * 256 + u]);
    d[base + 6] = __float2half(s3[k * 256 + u]);
}

__global__ void packWout(const float* __restrict__ Wout) {
    int n = blockIdx.x * blockDim.x + threadIdx.x;   // 0..31999
    int k = blockIdx.y;                              // 0..255
    if (n < NCLASS) {
        ((__half*)g_Wouth)[((size_t)(k >> 1) * NCLASS + n) * 2 + (k & 1)] =
            __float2half(Wout[(size_t)k * NCLASS + n]);
    }
}

// U1h pack + bias pack + barrier zero
__global__ void pack_misc(const float* Ui1, const float* Uf1,
                          const float* Uc1, const float* Uo1,
                          const float* bi, const float* bf,
                          const float* bc, const float* bo) {
    int b = blockIdx.x, tid = threadIdx.x;
    if (b < 128) {
        int k = b, u = tid;
        __half* d = (__half*)g_U1h;
        size_t base = ((size_t)(k >> 1) * 1024 + 4 * u) * 2 + (k & 1);
        d[base + 0] = __float2half(Ui1[k * 256 + u]);
        d[base + 2] = __float2half(Uf1[k * 256 + u]);
        d[base + 4] = __float2half(Uc1[k * 256 + u]);
        d[base + 6] = __float2half(Uo1[k * 256 + u]);
    } else {
        g_bp[4 * tid + 0] = bi[tid];
        g_bp[4 * tid + 1] = bf[tid];
        g_bp[4 * tid + 2] = bc[tid];
        g_bp[4 * tid + 3] = bo[tid];
        if (tid < 32) g_bar[tid] = 0;
    }
}

__global__ void dummy_k() {}

// ==========================================================================
// xU: xS[t*2048+b][c] = f16(C[X[b][t]]) @ U1h + bp.  M=524288, N=1024, K=128.
// CTA 128x128, fp16 mma.  smem: sW[64][132] + sA[128][68] (dynamic, 68608B)
// ==========================================================================
#define XU_SMEM 68608
__global__ __launch_bounds__(256) void xu_gemm(const int* __restrict__ X,
                                               const float* __restrict__ C) {
    extern __shared__ unsigned sm_xu[];
    unsigned* sw = sm_xu;            // [k2<64][132]
    unsigned* sa = sm_xu + 64 * 132; // [row<128][68]
    const int tid = threadIdx.x;
    const int w = tid >> 5, l = tid & 31;
    const int gid = l >> 2, tig = l & 3;
    const int wR = w >> 2, wC = w & 3;
    const int mBase = blockIdx.y * 128;
    const int nBase = blockIdx.x * 128;

    // stage W (64 k2 x 128 cols)
#pragma unroll
    for (int i = 0; i < 8; ++i) {
        int q = tid + i * 256;             // 2048 = 64*32
        int k2 = q >> 5, c4 = q & 31;
        *(uint4*)&sw[k2 * 132 + c4 * 4] = *(const uint4*)&g_U1h[k2 * 1024 + nBase + c4 * 4];
    }
    // stage A: gather token row, cvt fp32->fp16
    {
        int r = tid >> 1, part = tid & 1;
        int r_glob = mBase + r;
        int t_idx = r_glob >> 11, b_idx = r_glob & 2047;
        int tok = X[b_idx * TT + t_idx];
        const float* src = C + (size_t)tok * EMB + part * 64;
#pragma unroll
        for (int j = 0; j < 8; ++j) {
            float4 v0 = *(const float4*)&src[j * 8];
            float4 v1 = *(const float4*)&src[j * 8 + 4];
            uint4 o;
            o.x = h2u(__floats2half2_rn(v0.x, v0.y));
            o.y = h2u(__floats2half2_rn(v0.z, v0.w));
            o.z = h2u(__floats2half2_rn(v1.x, v1.y));
            o.w = h2u(__floats2half2_rn(v1.z, v1.w));
            *(uint4*)&sa[r * 68 + part * 32 + j * 4] = o;
        }
    }
    __syncthreads();

    float acc[4][4][4];
#pragma unroll
    for (int mt = 0; mt < 4; ++mt)
#pragma unroll
        for (int nt = 0; nt < 4; ++nt)
#pragma unroll
            for (int q = 0; q < 4; ++q) acc[mt][nt][q] = 0.f;

#pragma unroll
    for (int ki = 0; ki < 8; ++ki) {
        const int kb = ki * 8;
        unsigned bf_[4][2];
#pragma unroll
        for (int nt = 0; nt < 4; ++nt) {
            int c = wC * 32 + nt * 8 + gid;
            bf_[nt][0] = sw[(kb + tig) * 132 + c];
            bf_[nt][1] = sw[(kb + 4 + tig) * 132 + c];
        }
#pragma unroll
        for (int mt = 0; mt < 4; ++mt) {
            int r = wR * 64 + mt * 16 + gid;
            unsigned a0 = sa[r * 68 + kb + tig];
            unsigned a1 = sa[(r + 8) * 68 + kb + tig];
            unsigned a2 = sa[r * 68 + kb + 4 + tig];
            unsigned a3 = sa[(r + 8) * 68 + kb + 4 + tig];
#pragma unroll
            for (int nt = 0; nt < 4; ++nt)
                mma_f16(acc[mt][nt], a0, a1, a2, a3, bf_[nt][0], bf_[nt][1]);
        }
    }

    const int t_tile = mBase >> 11;
    __half* xu = (t_tile < 128) ? g_xS0 : g_xS1;
    const size_t rowoff = (size_t)(mBase & ((128 << 11) - 1));
#pragma unroll
    for (int nt = 0; nt < 4; ++nt) {
        int c0 = nBase + wC * 32 + nt * 8 + 2 * tig;
        float2 bb = *(const float2*)&g_bp[c0];
#pragma unroll
        for (int mt = 0; mt < 4; ++mt) {
            int r0 = wR * 64 + mt * 16 + gid;
            __half2 v0 = __floats2half2_rn(acc[mt][nt][0] + bb.x, acc[mt][nt][1] + bb.y);
            __half2 v1 = __floats2half2_rn(acc[mt][nt][2] + bb.x, acc[mt][nt][3] + bb.y);
            *(__half2*)&xu[(rowoff + r0) * 1024 + c0] = v0;
            *(__half2*)&xu[(rowoff + r0 + 8) * 1024 + c0] = v1;
        }
    }
}

// ==========================================================================
// Persistent LSTM phase, fp16 MMA, weights SMEM-resident.
//   layer 0: gates(t) = h1(t-1)@V1 + xS[t]           (K=256)
//   layer 1: gates(t) = h1all[t]@U2 [pre-barrier] + h2(t-1)@V2 + b (K=512)
// 128 CTAs: 16 row groups x 8 n-slices.  c-state in registers.
// smem: sW[256][132] (135168B) + sA[128][132] (67584B) = 202752B
// ==========================================================================
#define PH_SMEM 202752
__global__ __launch_bounds__(256) void lstm_phase(int layer) {
    extern __shared__ unsigned sm_ph[];
    unsigned* sw = sm_ph;                 // [k2][132]
    unsigned* sa = sm_ph + 256 * 132;     // [row][132]

    const int tid = threadIdx.x;
    const int w = tid >> 5, l = tid & 31;
    const int gid = l >> 2, tig = l & 3;
    const int wR = w >> 2, wC = w & 3;
    const int mg = blockIdx.x >> 3, ng = blockIdx.x & 7;
    const int mBase = mg << 7;
    const int ubase = ng << 5;

    const unsigned* Wsrc = layer ? g_W2h : g_W1h;
    const int k2tot = layer ? 256 : 128;
    __half* hall = layer ? g_h2h : g_h1h;
    int* bar = g_bar + (layer ? 16 : 0);
    const int nBase = ng << 7;

    // load weight slice once
    for (int q = tid; q < k2tot * 32; q += 256) {
        int k2 = q >> 5, c4 = q & 31;
        *(uint4*)&sw[k2 * 132 + c4 * 4] = *(const uint4*)&Wsrc[k2 * 1024 + nBase + c4 * 4];
    }

    float creg[4][4];
#pragma unroll
    for (int a = 0; a < 4; ++a)
#pragma unroll
        for (int b = 0; b < 4; ++b) creg[a][b] = 0.f;

    __syncthreads();

#pragma unroll 1
    for (int t = 0; t < TT; ++t) {
        float acc[4][4][4];
#pragma unroll
        for (int mt = 0; mt < 4; ++mt)
#pragma unroll
            for (int nt = 0; nt < 4; ++nt)
#pragma unroll
                for (int q = 0; q < 4; ++q) acc[mt][nt][q] = 0.f;

        // ---- layer 1 only: chunk 0 = h1all[t] @ U2 — NO barrier dependency ----
        if (layer == 1) {
            const __half* hsrc = g_h1h + (size_t)t * BB * NH;
#pragma unroll
            for (int i = 0; i < 16; ++i) {
                int q = tid + i * 256;
                int r = q >> 5, c = q & 31;
                *(uint4*)&sa[r * 132 + c * 4] =
                    *(const uint4*)(hsrc + (size_t)(mBase + r) * NH + c * 8);
            }
            __syncthreads();
#pragma unroll 4
            for (int ki = 0; ki < 16; ++ki) {
                const int kb = ki * 8;
                unsigned bf_[4][2];
#pragma unroll
                for (int nt = 0; nt < 4; ++nt) {
                    int c = wC * 32 + nt * 8 + gid;
                    bf_[nt][0] = sw[(kb + tig) * 132 + c];
                    bf_[nt][1] = sw[(kb + 4 + tig) * 132 + c];
                }
#pragma unroll
                for (int mt = 0; mt < 4; ++mt) {
                    int r = wR * 64 + mt * 16 + gid;
                    unsigned a0 = sa[r * 132 + kb + tig];
                    unsigned a1 = sa[(r + 8) * 132 + kb + tig];
                    unsigned a2 = sa[r * 132 + kb + 4 + tig];
                    unsigned a3 = sa[(r + 8) * 132 + kb + 4 + tig];
#pragma unroll
                    for (int nt = 0; nt < 4; ++nt)
                        mma_f16(acc[mt][nt], a0, a1, a2, a3, bf_[nt][0], bf_[nt][1]);
                }
            }
            __syncthreads();   // sa reads done before restage
        }

        // ---- barrier: wait for h(t-1) of this row group ----
        if (t > 0) {
            if (tid == 0) {
                int target = t << 3;
                while (ld_acquire(&bar[mg]) < target) __nanosleep(40);
            }
            __syncthreads();
        }

        // ---- recurrent chunk: h(t-1) @ V ----
        {
            const __half* hsrc = (t == 0) ? g_hzh : hall + (size_t)(t - 1) * BB * NH;
#pragma unroll
            for (int i = 0; i < 16; ++i) {
                int q = tid + i * 256;
                int r = q >> 5, c = q & 31;
                *(uint4*)&sa[r * 132 + c * 4] =
                    *(const uint4*)(hsrc + (size_t)(mBase + r) * NH + c * 8);
            }
            __syncthreads();

            const int kw0 = layer ? 128 : 0;
#pragma unroll 4
            for (int ki = 0; ki < 16; ++ki) {
                const int kb = ki * 8;
                unsigned bf_[4][2];
#pragma unroll
                for (int nt = 0; nt < 4; ++nt) {
                    int c = wC * 32 + nt * 8 + gid;
                    bf_[nt][0] = sw[(kw0 + kb + tig) * 132 + c];
                    bf_[nt][1] = sw[(kw0 + kb + 4 + tig) * 132 + c];
                }
#pragma unroll
                for (int mt = 0; mt < 4; ++mt) {
                    int r = wR * 64 + mt * 16 + gid;
                    unsigned a0 = sa[r * 132 + kb + tig];
                    unsigned a1 = sa[(r + 8) * 132 + kb + tig];
                    unsigned a2 = sa[r * 132 + kb + 4 + tig];
                    unsigned a3 = sa[(r + 8) * 132 + kb + 4 + tig];
#pragma unroll
                    for (int nt = 0; nt < 4; ++nt)
                        mma_f16(acc[mt][nt], a0, a1, a2, a3, bf_[nt][0], bf_[nt][1]);
                }
            }
        }

        // ---- epilogue: LSTM cell; h(fp16) -> sH -> coalesced GMEM ----
        __syncthreads();                       // all mma reads of sa done
        __half* sH = (__half*)sa;              // [32 units][132]
        const __half* xrow = nullptr;
        if (layer == 0) {
            const __half* xs = (t < 128) ? g_xS0 : g_xS1;
            xrow = xs + (size_t)(t & 127) * BB * 1024;
        }
        const bool tlow = ((tig & 1) == 0);
#pragma unroll
        for (int nt = 0; nt < 4; ++nt) {
            int c0l = wC * 32 + nt * 8 + 2 * tig;
            int nl = c0l >> 2;
#pragma unroll
            for (int mt = 0; mt < 4; ++mt) {
                float q0 = acc[mt][nt][0], q1 = acc[mt][nt][1];
                float q2 = acc[mt][nt][2], q3 = acc[mt][nt][3];
                float x0 = tlow ? q2 : q0;
                float x1 = tlow ? q3 : q1;
                float y0 = __shfl_xor_sync(0xffffffffu, x0, 1);
                float y1 = __shfl_xor_sync(0xffffffffu, x1, 1);
                float gI, gF, gG, gO; int rl;
                if (tlow) { gI = q0; gF = q1; gG = y0; gO = y1; rl = wR * 64 + mt * 16 + gid; }
                else      { gI = y0; gF = y1; gG = q2; gO = q3; rl = wR * 64 + mt * 16 + gid + 8; }
                float a0, a1, a2, a3;
                if (layer == 0) {
                    uint2 xv = *(const uint2*)&xrow[(size_t)(mBase + rl) * 1024 +
                                                    ((ubase + nl) << 2)];
                    __half2 p0 = *reinterpret_cast<__half2*>(&xv.x);
                    __half2 p1 = *reinterpret_cast<__half2*>(&xv.y);
                    a0 = __low2float(p0); a1 = __high2float(p0);
                    a2 = __low2float(p1); a3 = __high2float(p1);
                } else {
                    float4 b4 = *(const float4*)&g_bp[(ubase + nl) << 2];
                    a0 = b4.x; a1 = b4.y; a2 = b4.z; a3 = b4.w;
                }
                float si = sigf(gI + a0);
                float sf = sigf(gF + a1);
                float sg = tanhfa(gG + a2);
                float so = sigf(gO + a3);
                float cn = creg[nt][mt] * sf + si * sg;
                creg[nt][mt] = cn;
                sH[nl * 132 + rl] = __float2half(so * tanhfa(cn));
            }
        }
        __syncthreads();

        __half* hdst = hall + (size_t)t * BB * NH;
#pragma unroll
        for (int i = 0; i < 8; ++i) {
            int q = tid + i * 256;           // 2048 = 128 rows x 16 half2
            int r = q >> 4, u2 = q & 15;
            __half2 hv = __halves2half2(sH[(2 * u2) * 132 + r],
                                        sH[(2 * u2 + 1) * 132 + r]);
            *(__half2*)(hdst + (size_t)(mBase + r) * NH + ubase + 2 * u2) = hv;
        }
        __syncthreads();                     // sH reads done; stores issued
        if (tid == 0) red_release(&bar[mg]); // release: orders h stores before count
    }
}

// ==========================================================================
// Output GEMM: out = h2(255) @ W_out + b_out.  fp16 mma.  M=2048,N=32000,K=256
// smem: sW[128][132] + sA[128][132] = 135168B
// ==========================================================================
#define OUT_SMEM 135168
__global__ __launch_bounds__(256) void out_gemm(const float* __restrict__ bout,
                                                float* __restrict__ out) {
    extern __shared__ unsigned sm_o[];
    unsigned* sw = sm_o;
    unsigned* sa = sm_o + 128 * 132;
    const int tid = threadIdx.x;
    const int w = tid >> 5, l = tid & 31;
    const int gid = l >> 2, tig = l & 3;
    const int wR = w >> 2, wC = w & 3;
    const int mBase = blockIdx.y * 128;
    const int nBase = blockIdx.x * 128;
    const __half* h2 = g_h2h + (size_t)(TT - 1) * BB * NH;

    // stage W (128 k2 x 128 cols)
#pragma unroll
    for (int i = 0; i < 16; ++i) {
        int q = tid + i * 256;
        int k2 = q >> 5, c4 = q & 31;
        *(uint4*)&sw[k2 * 132 + c4 * 4] =
            *(const uint4*)&g_Wouth[(size_t)k2 * NCLASS + nBase + c4 * 4];
    }
    // stage A (pure copy of fp16 h2)
#pragma unroll
    for (int i = 0; i < 16; ++i) {
        int q = tid + i * 256;
        int r = q >> 5, c = q & 31;
        *(uint4*)&sa[r * 132 + c * 4] =
            *(const uint4*)(h2 + (size_t)(mBase + r) * NH + c * 8);
    }
    __syncthreads();

    float acc[4][4][4];
#pragma unroll
    for (int mt = 0; mt < 4; ++mt)
#pragma unroll
        for (int nt = 0; nt < 4; ++nt)
#pragma unroll
            for (int q = 0; q < 4; ++q) acc[mt][nt][q] = 0.f;

#pragma unroll 4
    for (int ki = 0; ki < 16; ++ki) {
        const int kb = ki * 8;
        unsigned bf_[4][2];
#pragma unroll
        for (int nt = 0; nt < 4; ++nt) {
            int c = wC * 32 + nt * 8 + gid;
            bf_[nt][0] = sw[(kb + tig) * 132 + c];
            bf_[nt][1] = sw[(kb + 4 + tig) * 132 + c];
        }
#pragma unroll
        for (int mt = 0; mt < 4; ++mt) {
            int r = wR * 64 + mt * 16 + gid;
            unsigned a0 = sa[r * 132 + kb + tig];
            unsigned a1 = sa[(r + 8) * 132 + kb + tig];
            unsigned a2 = sa[r * 132 + kb + 4 + tig];
            unsigned a3 = sa[(r + 8) * 132 + kb + 4 + tig];
#pragma unroll
            for (int nt = 0; nt < 4; ++nt)
                mma_f16(acc[mt][nt], a0, a1, a2, a3, bf_[nt][0], bf_[nt][1]);
        }
    }

#pragma unroll
    for (int nt = 0; nt < 4; ++nt) {
        int c0 = nBase + wC * 32 + nt * 8 + 2 * tig;
        float2 bb = *(const float2*)&bout[c0];
#pragma unroll
        for (int mt = 0; mt < 4; ++mt) {
            int r0 = mBase + wR * 64 + mt * 16 + gid;
            float2 v0 = make_float2(acc[mt][nt][0] + bb.x, acc[mt][nt][1] + bb.y);
            float2 v1 = make_float2(acc[mt][nt][2] + bb.x, acc[mt][nt][3] + bb.y);
            *(float2*)&out[(size_t)r0 * NCLASS + c0] = v0;
            *(float2*)&out[(size_t)(r0 + 8) * NCLASS + c0] = v1;
        }
    }
}

// -------- launch --------
extern "C" void kernel_launch(void* const* d_in, const int* in_sizes, int n_in,
                              void* d_out, int out_size) {
    (void)in_sizes; (void)n_in; (void)out_size;
    const int*   X    = (const int*)d_in[0];
    const float* C    = (const float*)d_in[1];
    const float* Ui1  = (const float*)d_in[2];
    const float* Vi1  = (const float*)d_in[3];
    const float* Ui2  = (const float*)d_in[4];
    const float* Vi2  = (const float*)d_in[5];
    const float* bi   = (const float*)d_in[6];
    const float* Uf1  = (const float*)d_in[7];
    const float* Vf1  = (const float*)d_in[8];
    const float* Uf2  = (const float*)d_in[9];
    const float* Vf2  = (const float*)d_in[10];
    const float* bf   = (const float*)d_in[11];
    const float* Uc1  = (const float*)d_in[12];
    const float* Vc1  = (const float*)d_in[13];
    const float* Uc2  = (const float*)d_in[14];
    const float* Vc2  = (const float*)d_in[15];
    const float* bc   = (const float*)d_in[16];
    const float* Uo1  = (const float*)d_in[17];
    const float* Vo1  = (const float*)d_in[18];
    const float* Uo2  = (const float*)d_in[19];
    const float* Vo2  = (const float*)d_in[20];
    const float* bo   = (const float*)d_in[21];
    const float* Wout = (const float*)d_in[22];
    const float* bout = (const float*)d_in[23];
    float* out = (float*)d_out;

    cudaFuncSetAttribute(lstm_phase, cudaFuncAttributeMaxDynamicSharedMemorySize, PH_SMEM);
    cudaFuncSetAttribute(xu_gemm,    cudaFuncAttributeMaxDynamicSharedMemorySize, XU_SMEM);
    cudaFuncSetAttribute(out_gemm,   cudaFuncAttributeMaxDynamicSharedMemorySize, OUT_SMEM);

    // #1: all recurrent weight packing in one launch
    pack4h_all<<<dim3(256, 3), 256>>>(Vi1, Vf1, Vc1, Vo1,
                                      Ui2, Uf2, Uc2, Uo2,
                                      Vi2, Vf2, Vc2, Vo2);
    // #2, #3
    packWout<<<dim3(125, 256), 256>>>(Wout);
    pack_misc<<<129, 256>>>(Ui1, Uf1, Uc1, Uo1, bi, bf, bc, bo);

    // #4: xU = embed @ U1 + b
    xu_gemm<<<dim3(8, 4096), 256, XU_SMEM>>>(X, C);

    // #5: dummy (positions phase A at launch #6 for ncu -s 5 -c 1)
    dummy_k<<<1, 32>>>();

    // #6: phase A — layer-1 recurrence
    lstm_phase<<<128, 256, PH_SMEM>>>(0);

    // #7: phase C — layer-2 recurrence (U2 projection folded, pre-barrier)
    lstm_phase<<<128, 256, PH_SMEM>>>(1);

    // #8: output projection
    out_gemm<<<dim3(NCLASS / 128, BB / 128), 256, OUT_SMEM>>>(bout, out);
}